// round 11
// baseline (speedup 1.0000x reference)
#include <cuda_runtime.h>
#include <math.h>
#include <stdint.h>

#define BATCH 8
#define NPIX 4096
#define CCH 64
#define HID 128
#define ATT_SCALE 0.25f

static __device__ float g_Wswz[9 * 128 * 64];    // pre-swizzled tf32 conv weights [tap][o][64]
static __device__ float g_QKVswz[192 * 64];      // pre-swizzled tf32 qkv weights [o][64]
static __device__ float g_FC1swz[64 * 128];      // pre-swizzled tf32 fc1 weights [o][128]
static __device__ float g_OUTp[64 * 66];         // pair-interleaved tf32 weights
static __device__ float g_FF1p[64 * 66];
static __device__ float g_FF2p[64 * 66];
static __device__ float g_beff[HID];
static __device__ float g_xbuf[2][BATCH * NPIX * CCH];
static __device__ float g_part[256 * 2];
static __device__ float g_q[BATCH * NPIX * CCH];
static __device__ float g_k[BATCH * NPIX * CCH];
static __device__ float g_v[BATCH * NPIX * CCH];
static __device__ int g_maskmode;
static __device__ unsigned g_barrier;            // monotonic ticket counter

__device__ __forceinline__ uint32_t f2tf32(float f) {
    uint32_t u;
    asm("cvt.rna.tf32.f32 %0, %1;" : "=r"(u) : "f"(f));
    return u;
}

__device__ __forceinline__ int swz_pos(int c, int par) {
    int t4 = c & 3, idx = c >> 2;
    int pi = (t4 * 4 + (((idx >> 2) + t4) & 3)) ^ par;
    return pi * 4 + (idx & 3);
}

__device__ __forceinline__ int pairpos(int k) {
    return (k & 56) + ((k & 3) << 1) + ((k >> 2) & 1);
}

// ticket grid barrier: all 256 blocks resident (2/SM x 148 SM = 296 slots).
__device__ __forceinline__ void grid_barrier() {
    __shared__ unsigned s_target;
    __threadfence();
    __syncthreads();
    if (threadIdx.x == 0) {
        unsigned ticket = atomicAdd(&g_barrier, 1u);
        s_target = (ticket / 256u + 1u) * 256u;
    }
    __syncthreads();
    if (threadIdx.x == 0) {
        while (*((volatile unsigned*)&g_barrier) < s_target) { }
        __threadfence();
    }
    __syncthreads();
}

__global__ void k_maskdetect(const unsigned char* m, int nbytes) {
    __shared__ int hasBig, hasMis;
    if (threadIdx.x == 0) { hasBig = 0; hasMis = 0; }
    __syncthreads();
    for (int i = threadIdx.x; i < nbytes; i += blockDim.x) {
        unsigned char v = m[i];
        if (v > 1) hasBig = 1;
        else if (v && (i & 3)) hasMis = 1;
    }
    __syncthreads();
    if (threadIdx.x == 0) g_maskmode = (!hasBig && hasMis) ? 1 : 0;
}

__global__ void k_fold(const float* __restrict__ fc0_w, const float* __restrict__ fc0_b,
                       const float* __restrict__ p0_w, const float* __restrict__ p0_b,
                       const float* __restrict__ p1_w, const float* __restrict__ p1_b) {
    int t = blockIdx.x * 256 + threadIdx.x;
    if (t >= HID * 576) return;
    int o = t / 576, k = t - o * 576;
    int tap = k >> 6, c = k & 63;
    const float* f1 = fc0_w + o * 192 + 64;
    const float* f2 = fc0_w + o * 192 + 128;
    float acc = 0.f;
    for (int m = 0; m < 64; m++) {
        acc = fmaf(f1[m], p0_w[(m * 64 + c) * 9 + tap], acc);
        acc = fmaf(f2[m], p1_w[(m * 64 + c) * 9 + tap], acc);
    }
    if (tap == 4) acc += fc0_w[o * 192 + c];
    g_Wswz[(tap * 128 + o) * 64 + swz_pos(c, o & 1)] = __uint_as_float(f2tf32(acc));
    if (k == 0) {
        float b = fc0_b[o];
        for (int m = 0; m < 64; m++) {
            b = fmaf(f1[m], p0_b[m], b);
            b = fmaf(f2[m], p1_b[m], b);
        }
        g_beff[o] = b;
    }
}

__global__ void k_prepw(const float* __restrict__ qkvw, const float* __restrict__ fc1w,
                        const float* __restrict__ outw, const float* __restrict__ ff1w,
                        const float* __restrict__ ff2w) {
    int t = blockIdx.x * 256 + threadIdx.x;
    if (t < 192 * 64) {
        int o = t >> 6, k = t & 63;
        g_QKVswz[o * 64 + swz_pos(k, o & 1)] = __uint_as_float(f2tf32(qkvw[t]));
    }
    if (t < 64 * 128) {
        int o = t >> 7, k = t & 127;
        int half = k >> 6, kk = k & 63;
        g_FC1swz[o * 128 + half * 64 + swz_pos(kk, o & 1)] = __uint_as_float(f2tf32(fc1w[t]));
    }
    if (t < 64 * 64) {
        int c = t >> 6, k = t & 63;
        int p = c * 66 + pairpos(k);
        g_OUTp[p] = __uint_as_float(f2tf32(outw[t]));
        g_FF1p[p] = __uint_as_float(f2tf32(ff1w[t]));
        g_FF2p[p] = __uint_as_float(f2tf32(ff2w[t]));
    }
    if (t < 128) {
        int c = t >> 1, pos = 64 + (t & 1);
        g_OUTp[c * 66 + pos] = 0.f;
        g_FF1p[c * 66 + pos] = 0.f;
        g_FF2p[c * 66 + pos] = 0.f;
    }
    if (t == 0 && blockIdx.x == 0) { /* keep g_barrier monotonic; no reset */ }
}

__device__ __forceinline__ int refl(int v) { return v < 0 ? -v : (v > 63 ? 126 - v : v); }

__device__ __forceinline__ void mma_tf32(float* c, const uint32_t* a, uint32_t b0, uint32_t b1) {
    asm volatile(
        "mma.sync.aligned.m16n8k8.row.col.f32.tf32.tf32.f32 "
        "{%0,%1,%2,%3}, {%4,%5,%6,%7}, {%8,%9}, {%0,%1,%2,%3};"
        : "+f"(c[0]), "+f"(c[1]), "+f"(c[2]), "+f"(c[3])
        : "r"(a[0]), "r"(a[1]), "r"(a[2]), "r"(a[3]), "r"(b0), "r"(b1));
}

// 16px x 32out x K64 per warp on pair-interleaved stride-66 operands
__device__ __forceinline__ void gemm_66(const float* __restrict__ Ap,
                                        const float* __restrict__ Wp,
                                        int rbase, int nw, int g, int t4,
                                        float acc[4][4]) {
    #pragma unroll
    for (int k0 = 0; k0 < 8; k0++) {
        int kb = k0 * 8 + 2 * t4;
        float2 a0 = *(const float2*)&Ap[(rbase + g) * 66 + kb];
        float2 a1 = *(const float2*)&Ap[(rbase + g + 8) * 66 + kb];
        uint32_t a[4] = {__float_as_uint(a0.x), __float_as_uint(a1.x),
                         __float_as_uint(a0.y), __float_as_uint(a1.y)};
        #pragma unroll
        for (int n = 0; n < 4; n++) {
            float2 b = *(const float2*)&Wp[(nw * 32 + n * 8 + g) * 66 + kb];
            mma_tf32(acc[n], a, __float_as_uint(b.x), __float_as_uint(b.y));
        }
    }
}

// ================= MEGA kernel: conv + grid-barrier + stats + fc1 + qkv =================
// pool P[25088] floats = 100352 B, 2 blocks/SM, 256 blocks (all resident)
#define MEGA_SMEM_BYTES (25088 * 4)

__global__ void __launch_bounds__(256, 2) k_mega(const float* __restrict__ xin,
                                                 const float* __restrict__ nw0,
                                                 const float* __restrict__ nb0,
                                                 const void* __restrict__ mask, int s,
                                                 float* __restrict__ xout,
                                                 const float* __restrict__ lw,
                                                 const float* __restrict__ lb) {
    extern __shared__ float P[];
    __shared__ float s_mu, s_rs;
    int tid = threadIdx.x;
    int batch = blockIdx.x >> 5;
    int y0 = (blockIdx.x & 31) << 1;
    int p0 = y0 * 64;                       // first pixel of this 128-px tile
    const float* xb = xin + (size_t)batch * NPIX * CCH;
    int warp = tid >> 5, lane = tid & 31;
    int g = lane >> 2, t4 = lane & 3;

    // ---------- conv phase ----------
    {
        float* Xh = P;                      // [264][64]
        float* Wsh = P + 16896;             // [128][64]
        #pragma unroll 2
        for (int i = 0; i < 66; i++) {
            int lin = i * 256 + tid;
            int ch = lin & 63;
            int hp = lin >> 6;
            int hr = hp / 66, hc = hp - hr * 66;
            int gy = refl(y0 + hr - 1), gx = refl(hc - 1);
            float v = xb[(gy * 64 + gx) * CCH + ch];
            Xh[hp * 64 + swz_pos(ch, hp & 1)] = __uint_as_float(f2tf32(v));
        }
        int pixBase = (warp >> 1) * 32;
        int nBase = (warp & 1) * 64;

        float acc[2][8][4];
        #pragma unroll
        for (int m = 0; m < 2; m++)
            #pragma unroll
            for (int n = 0; n < 8; n++)
                #pragma unroll
                for (int j2 = 0; j2 < 4; j2++) acc[m][n][j2] = 0.f;

        for (int tap = 0; tap < 9; tap++) {
            int dy = tap / 3, dx = tap - dy * 3;
            __syncthreads();
            {
                const float4* wsrc = (const float4*)(g_Wswz + tap * (128 * 64));
                float4* wdst = (float4*)Wsh;
                #pragma unroll
                for (int i = 0; i < 8; i++) wdst[i * 256 + tid] = wsrc[i * 256 + tid];
            }
            __syncthreads();
            #pragma unroll
            for (int j = 0; j < 4; j++) {
                int pibase = t4 * 4 + ((j + t4) & 3);
                float4 av[4];
                #pragma unroll
                for (int r = 0; r < 4; r++) {
                    int pr = pixBase + r * 8 + g;
                    int hb = ((pr >> 6) + dy) * 66 + (pr & 63) + dx;
                    av[r] = *(const float4*)&Xh[hb * 64 + ((pibase ^ (hb & 1)) << 2)];
                }
                uint32_t aH0m0[4] = {__float_as_uint(av[0].x), __float_as_uint(av[1].x),
                                     __float_as_uint(av[0].y), __float_as_uint(av[1].y)};
                uint32_t aH1m0[4] = {__float_as_uint(av[0].z), __float_as_uint(av[1].z),
                                     __float_as_uint(av[0].w), __float_as_uint(av[1].w)};
                uint32_t aH0m1[4] = {__float_as_uint(av[2].x), __float_as_uint(av[3].x),
                                     __float_as_uint(av[2].y), __float_as_uint(av[3].y)};
                uint32_t aH1m1[4] = {__float_as_uint(av[2].z), __float_as_uint(av[3].z),
                                     __float_as_uint(av[2].w), __float_as_uint(av[3].w)};
                #pragma unroll
                for (int n = 0; n < 8; n++) {
                    int o = nBase + n * 8 + g;
                    float4 bv = *(const float4*)&Wsh[o * 64 + ((pibase ^ (o & 1)) << 2)];
                    uint32_t b0 = __float_as_uint(bv.x), b1 = __float_as_uint(bv.y);
                    uint32_t b2 = __float_as_uint(bv.z), b3 = __float_as_uint(bv.w);
                    mma_tf32(acc[0][n], aH0m0, b0, b1);
                    mma_tf32(acc[0][n], aH1m0, b2, b3);
                    mma_tf32(acc[1][n], aH0m1, b0, b1);
                    mma_tf32(acc[1][n], aH1m1, b2, b3);
                }
            }
        }
        __syncthreads();

        // epilogue: bias+relu -> hd in P[0..16384), LN partial sums -> red
        float ssum = 0.f, sq = 0.f;
        #pragma unroll
        for (int m = 0; m < 2; m++) {
            int p_lo = pixBase + m * 16 + g;
            int p_hi = p_lo + 8;
            #pragma unroll
            for (int n = 0; n < 8; n++) {
                int col = nBase + n * 8 + 2 * t4;
                float bo0 = g_beff[col], bo1 = g_beff[col + 1];
                float r0 = fmaxf(acc[m][n][0] + bo0, 0.f);
                float r1 = fmaxf(acc[m][n][1] + bo1, 0.f);
                float r2 = fmaxf(acc[m][n][2] + bo0, 0.f);
                float r3 = fmaxf(acc[m][n][3] + bo1, 0.f);
                *(float2*)&P[p_lo * 128 + col] = make_float2(r0, r1);
                *(float2*)&P[p_hi * 128 + col] = make_float2(r2, r3);
                ssum += r0 + r1 + r2 + r3;
                sq += r0 * r0 + r1 * r1 + r2 * r2 + r3 * r3;
            }
        }
        float* red = P + 24576;
        red[tid] = ssum; red[256 + tid] = sq;
        __syncthreads();
        for (int st = 128; st > 0; st >>= 1) {
            if (tid < st) { red[tid] += red[tid + st]; red[256 + tid] += red[256 + tid + st]; }
            __syncthreads();
        }
        if (tid == 0) {
            g_part[blockIdx.x * 2] = red[0];
            g_part[blockIdx.x * 2 + 1] = red[256];
        }
    }

    // ---------- global LN stats across all blocks ----------
    grid_barrier();

    if (tid < 32) {
        float ss = g_part[(batch * 32 + tid) * 2];
        float sq = g_part[(batch * 32 + tid) * 2 + 1];
        #pragma unroll
        for (int o = 16; o > 0; o >>= 1) {
            ss += __shfl_xor_sync(0xffffffffu, ss, o);
            sq += __shfl_xor_sync(0xffffffffu, sq, o);
        }
        if (tid == 0) {
            const float inv = 1.f / 524288.f;
            float mu = ss * inv;
            s_mu = mu;
            s_rs = rsqrtf(sq * inv - mu * mu + 1e-5f);
        }
    }
    // stage fc1 weights (independent of stats)
    {
        float* WF = P + 16384;
        const float4* wsrc = (const float4*)g_FC1swz;
        float4* wdst = (float4*)WF;
        #pragma unroll
        for (int i = 0; i < 8; i++) wdst[i * 256 + tid] = wsrc[i * 256 + tid];
    }
    __syncthreads();
    float mu = s_mu, rs = s_rs;

    // ---------- in-place LN + tf32 swizzle of hd (2 stages) ----------
    #pragma unroll
    for (int stg = 0; stg < 2; stg++) {
        float r[32];
        #pragma unroll
        for (int i = 0; i < 32; i++) {
            int lin = stg * 8192 + i * 256 + tid;
            r[i] = P[(lin >> 7) * 128 + (lin & 127)];
        }
        __syncthreads();
        #pragma unroll
        for (int i = 0; i < 32; i++) {
            int lin = stg * 8192 + i * 256 + tid;
            int pix = lin >> 7, kk = lin & 127;
            int ii = (p0 + pix) * HID + kk;
            float y = (r[i] - mu) * rs * nw0[ii] + nb0[ii];
            int half = kk >> 6, kc = kk & 63;
            P[pix * 128 + half * 64 + swz_pos(kc, pix & 1)] = __uint_as_float(f2tf32(y));
        }
        __syncthreads();
    }

    // ---------- fc1 MMA: 128px x 64out x K128 ----------
    int mwf = warp >> 1, nwf = warp & 1;
    int pixBaseF = mwf * 32, oBaseF = nwf * 32;
    {
        float* WF = P + 16384;
        float accf[2][4][4];
        #pragma unroll
        for (int m = 0; m < 2; m++)
            #pragma unroll
            for (int n = 0; n < 4; n++)
                #pragma unroll
                for (int j = 0; j < 4; j++) accf[m][n][j] = 0.f;

        #pragma unroll
        for (int half = 0; half < 2; half++) {
            #pragma unroll
            for (int j = 0; j < 4; j++) {
                int pibase = t4 * 4 + ((j + t4) & 3);
                float4 av[4];
                #pragma unroll
                for (int r = 0; r < 4; r++) {
                    int pr = pixBaseF + r * 8 + g;
                    av[r] = *(const float4*)&P[pr * 128 + half * 64 + ((pibase ^ (pr & 1)) << 2)];
                }
                uint32_t aH0m0[4] = {__float_as_uint(av[0].x), __float_as_uint(av[1].x),
                                     __float_as_uint(av[0].y), __float_as_uint(av[1].y)};
                uint32_t aH1m0[4] = {__float_as_uint(av[0].z), __float_as_uint(av[1].z),
                                     __float_as_uint(av[0].w), __float_as_uint(av[1].w)};
                uint32_t aH0m1[4] = {__float_as_uint(av[2].x), __float_as_uint(av[3].x),
                                     __float_as_uint(av[2].y), __float_as_uint(av[3].y)};
                uint32_t aH1m1[4] = {__float_as_uint(av[2].z), __float_as_uint(av[3].z),
                                     __float_as_uint(av[2].w), __float_as_uint(av[3].w)};
                #pragma unroll
                for (int n = 0; n < 4; n++) {
                    int o = oBaseF + n * 8 + g;
                    float4 bv = *(const float4*)&WF[o * 128 + half * 64 + ((pibase ^ (o & 1)) << 2)];
                    uint32_t b0 = __float_as_uint(bv.x), b1 = __float_as_uint(bv.y);
                    uint32_t b2 = __float_as_uint(bv.z), b3 = __float_as_uint(bv.w);
                    mma_tf32(accf[0][n], aH0m0, b0, b1);
                    mma_tf32(accf[0][n], aH1m0, b2, b3);
                    mma_tf32(accf[1][n], aH0m1, b0, b1);
                    mma_tf32(accf[1][n], aH1m1, b2, b3);
                }
            }
        }
        __syncthreads();   // WF + fc1-A reads complete; xsh may overwrite WF region

        float* xsh = P + 16384;   // [128][64]
        int mode = g_maskmode;
        #pragma unroll
        for (int m = 0; m < 2; m++) {
            int p_lo = pixBaseF + m * 16 + g;
            int p_hi = p_lo + 8;
            size_t gplo = (size_t)batch * NPIX + p0 + p_lo;
            size_t gphi = (size_t)batch * NPIX + p0 + p_hi;
            size_t milo = (size_t)s * 32768 + gplo;
            size_t mihi = (size_t)s * 32768 + gphi;
            float mvlo, mvhi;
            if (mode) {
                mvlo = ((const unsigned char*)mask)[milo] ? 1.f : 0.f;
                mvhi = ((const unsigned char*)mask)[mihi] ? 1.f : 0.f;
            } else {
                mvlo = ((const unsigned int*)mask)[milo] ? 1.f : 0.f;
                mvhi = ((const unsigned int*)mask)[mihi] ? 1.f : 0.f;
            }
            #pragma unroll
            for (int n = 0; n < 4; n++) {
                int col = oBaseF + n * 8 + 2 * t4;
                float2 x0 = *(const float2*)&xin[gplo * CCH + col];
                float2 x1 = *(const float2*)&xin[gphi * CCH + col];
                float2 o0 = make_float2(x0.x + accf[m][n][0] * mvlo, x0.y + accf[m][n][1] * mvlo);
                float2 o1 = make_float2(x1.x + accf[m][n][2] * mvhi, x1.y + accf[m][n][3] * mvhi);
                *(float2*)&xout[gplo * CCH + col] = o0;
                *(float2*)&xout[gphi * CCH + col] = o1;
                *(float2*)&xsh[p_lo * 64 + col] = o0;
                *(float2*)&xsh[p_hi * 64 + col] = o1;
            }
        }
    }
    __syncthreads();

    // ---------- LN1 -> ysh2 (P[0..8192)) ----------
    {
        float* xsh = P + 16384;
        #pragma unroll
        for (int k = 0; k < 16; k++) {
            int pix = warp * 16 + k;
            float v0 = xsh[pix * 64 + lane], v1 = xsh[pix * 64 + lane + 32];
            float ss = v0 + v1, sq = v0 * v0 + v1 * v1;
            #pragma unroll
            for (int o = 16; o > 0; o >>= 1) {
                ss += __shfl_xor_sync(0xffffffffu, ss, o);
                sq += __shfl_xor_sync(0xffffffffu, sq, o);
            }
            float mu2 = ss * (1.f / 64.f);
            float rsg = rsqrtf(sq * (1.f / 64.f) - mu2 * mu2 + 1e-5f);
            float y0v = (v0 - mu2) * rsg * lw[lane] + lb[lane];
            float y1v = (v1 - mu2) * rsg * lw[lane + 32] + lb[lane + 32];
            P[pix * 64 + swz_pos(lane, pix & 1)] = __uint_as_float(f2tf32(y0v));
            P[pix * 64 + swz_pos(lane + 32, pix & 1)] = __uint_as_float(f2tf32(y1v));
        }
    }
    __syncthreads();
    // stage qkv weights (P[8192..20480); xsh dead after LN1)
    {
        float* WQ = P + 8192;
        const float4* wsrc = (const float4*)g_QKVswz;
        float4* wdst = (float4*)WQ;
        #pragma unroll
        for (int i = 0; i < 12; i++) wdst[i * 256 + tid] = wsrc[i * 256 + tid];
    }
    __syncthreads();

    // ---------- qkv MMA: 128px x 192out x K64, two output passes ----------
    {
        float* WQ = P + 8192;
        #pragma unroll
        for (int pass = 0; pass < 2; pass++) {
            float accq[2][6][4];
            #pragma unroll
            for (int m = 0; m < 2; m++)
                #pragma unroll
                for (int n = 0; n < 6; n++)
                    #pragma unroll
                    for (int j = 0; j < 4; j++) accq[m][n][j] = 0.f;

            #pragma unroll
            for (int j = 0; j < 4; j++) {
                int pibase = t4 * 4 + ((j + t4) & 3);
                float4 av[4];
                #pragma unroll
                for (int r = 0; r < 4; r++) {
                    int pr = pixBaseF + r * 8 + g;
                    av[r] = *(const float4*)&P[pr * 64 + ((pibase ^ (pr & 1)) << 2)];
                }
                uint32_t aH0m0[4] = {__float_as_uint(av[0].x), __float_as_uint(av[1].x),
                                     __float_as_uint(av[0].y), __float_as_uint(av[1].y)};
                uint32_t aH1m0[4] = {__float_as_uint(av[0].z), __float_as_uint(av[1].z),
                                     __float_as_uint(av[0].w), __float_as_uint(av[1].w)};
                uint32_t aH0m1[4] = {__float_as_uint(av[2].x), __float_as_uint(av[3].x),
                                     __float_as_uint(av[2].y), __float_as_uint(av[3].y)};
                uint32_t aH1m1[4] = {__float_as_uint(av[2].z), __float_as_uint(av[3].z),
                                     __float_as_uint(av[2].w), __float_as_uint(av[3].w)};
                #pragma unroll
                for (int n = 0; n < 6; n++) {
                    int o = pass * 96 + nwf * 48 + n * 8 + g;
                    float4 bv = *(const float4*)&WQ[o * 64 + ((pibase ^ (o & 1)) << 2)];
                    uint32_t b0 = __float_as_uint(bv.x), b1 = __float_as_uint(bv.y);
                    uint32_t b2 = __float_as_uint(bv.z), b3 = __float_as_uint(bv.w);
                    mma_tf32(accq[0][n], aH0m0, b0, b1);
                    mma_tf32(accq[0][n], aH1m0, b2, b3);
                    mma_tf32(accq[1][n], aH0m1, b0, b1);
                    mma_tf32(accq[1][n], aH1m1, b2, b3);
                }
            }
            #pragma unroll
            for (int m = 0; m < 2; m++) {
                int p_lo = pixBaseF + m * 16 + g;
                int p_hi = p_lo + 8;
                size_t gplo = (size_t)batch * NPIX + p0 + p_lo;
                size_t gphi = (size_t)batch * NPIX + p0 + p_hi;
                #pragma unroll
                for (int n = 0; n < 6; n++) {
                    int col = pass * 96 + nwf * 48 + n * 8 + 2 * t4;
                    int region = col >> 6;
                    int c = col & 63;
                    float* dst = (region == 0) ? g_q : (region == 1) ? g_k : g_v;
                    *(float2*)&dst[gplo * CCH + c] = make_float2(accq[m][n][0], accq[m][n][1]);
                    *(float2*)&dst[gphi * CCH + c] = make_float2(accq[m][n][2], accq[m][n][3]);
                }
            }
        }
    }
}

// ========== fused attn + out-proj + ff, 64px tiles, 256 threads ==========
// floats: ksh 6464 + vsh 6464 (wshp 4224 overlays) + oshp/yshp 4224 + tsh 4224 + hshp 4224
#define AF_SMEM_BYTES (25600 * 4)

__global__ void __launch_bounds__(256) k_attn_ff(const float* __restrict__ xn,
                                                 const float* __restrict__ xprev,
                                                 const float* __restrict__ outb,
                                                 const float* __restrict__ lw2,
                                                 const float* __restrict__ lb2,
                                                 const float* __restrict__ b1,
                                                 const float* __restrict__ b2,
                                                 float* __restrict__ xout) {
    extern __shared__ float sm[];
    float* ksh = sm;                  // [64ch][101]
    float* vsh = sm + 6464;
    float* wshp = sm;                 // weight overlay [64][66]
    float* oshp = sm + 12928;         // [64][66]; reused as yshp
    float* tsh = sm + 17152;          // [64][66] fp32
    float* hshp = sm + 21376;         // [64][66]
    int tid = threadIdx.x;
    int b = blockIdx.x >> 6;
    int tile = blockIdx.x & 63;
    int tx0 = (tile & 7) << 3;
    int ty0 = (tile >> 3) << 3;
    int warp = tid >> 5, lane = tid & 31;
    int g = lane >> 2, t4 = lane & 3;
    int mw = warp & 3, nw = warp >> 2;

    // halo: 10x10 positions
    #pragma unroll
    for (int i = 0; i < 25; i++) {
        int lin = tid + i * 256;
        int pos = lin >> 6, ch = lin & 63;
        int hy = pos / 10, hx = pos - hy * 10;
        int gy = ty0 + hy - 1, gx = tx0 + hx - 1;
        float kv = 0.f, vv = 0.f;
        if ((unsigned)gy < 64u && (unsigned)gx < 64u) {
            size_t a = ((size_t)b * NPIX + gy * 64 + gx) * CCH + ch;
            kv = g_k[a]; vv = g_v[a];
        }
        ksh[ch * 101 + pos] = kv;
        vsh[ch * 101 + pos] = vv;
    }
    __syncthreads();

    // attention: warp -> (head = warp&3, pixel-half = warp>>2)
    {
        int head = warp & 3, ph = warp >> 2;
        int lp = ph * 32 + lane;
        int py = lp >> 3, px = lp & 7;
        int gy = ty0 + py, gx = tx0 + px;
        size_t qbase = ((size_t)b * NPIX + gy * 64 + gx) * CCH + head * 16;
        float q[16];
        #pragma unroll
        for (int i = 0; i < 4; i++) {
            float4 t4v = *(const float4*)&g_q[qbase + i * 4];
            q[i * 4] = t4v.x; q[i * 4 + 1] = t4v.y; q[i * 4 + 2] = t4v.z; q[i * 4 + 3] = t4v.w;
        }
        float lg[9];
        #pragma unroll
        for (int t = 0; t < 9; t++) {
            int pos = (py + t / 3) * 10 + px + t % 3;
            float d = 0.f;
            #pragma unroll
            for (int i = 0; i < 16; i++) d = fmaf(q[i], ksh[(head * 16 + i) * 101 + pos], d);
            lg[t] = d * ATT_SCALE;
        }
        float m = lg[0];
        #pragma unroll
        for (int t = 1; t < 9; t++) m = fmaxf(m, lg[t]);
        float e[9], ssum = 0.f;
        #pragma unroll
        for (int t = 0; t < 9; t++) { e[t] = __expf(lg[t] - m); ssum += e[t]; }
        float inv = 1.f / ssum;
        float o[16] = {};
        #pragma unroll
        for (int t = 0; t < 9; t++) {
            int pos = (py + t / 3) * 10 + px + t % 3;
            float a = e[t] * inv;
            #pragma unroll
            for (int i = 0; i < 16; i++) o[i] = fmaf(a, vsh[(head * 16 + i) * 101 + pos], o[i]);
        }
        #pragma unroll
        for (int i = 0; i < 16; i++)
            oshp[lp * 66 + pairpos(head * 16 + i)] = __uint_as_float(f2tf32(o[i]));
    }
    __syncthreads();

    // stage out-proj weights
    {
        const float4* wsrc = (const float4*)g_OUTp;
        float4* wdst = (float4*)wshp;
        #pragma unroll
        for (int i = 0; i < 5; i++) {
            int idx = i * 256 + tid;
            if (idx < 1056) wdst[idx] = wsrc[idx];
        }
    }
    __syncthreads();

    // out-proj + bias + residual -> tsh
    {
        float acc[4][4] = {{0}};
        gemm_66(oshp, wshp, mw * 16, nw, g, t4, acc);
        int r0 = mw * 16 + g, r1 = r0 + 8;
        int gp0 = (ty0 + (r0 >> 3)) * 64 + tx0 + (r0 & 7);
        int gp1 = (ty0 + (r1 >> 3)) * 64 + tx0 + (r1 & 7);
        size_t b0a = ((size_t)b * NPIX + gp0) * CCH;
        size_t b1a = ((size_t)b * NPIX + gp1) * CCH;
        #pragma unroll
        for (int n = 0; n < 4; n++) {
            int col = nw * 32 + n * 8 + 2 * t4;
            tsh[r0 * 66 + col]     = acc[n][0] + outb[col]     + xn[b0a + col];
            tsh[r0 * 66 + col + 1] = acc[n][1] + outb[col + 1] + xn[b0a + col + 1];
            tsh[r1 * 66 + col]     = acc[n][2] + outb[col]     + xn[b1a + col];
            tsh[r1 * 66 + col + 1] = acc[n][3] + outb[col + 1] + xn[b1a + col + 1];
        }
    }
    __syncthreads();

    // LN2 -> yshp (= oshp region); stage ff1 weights
    float* yshp = oshp;
    #pragma unroll
    for (int k = 0; k < 8; k++) {
        int pix = warp * 8 + k;
        float v0 = tsh[pix * 66 + lane], v1 = tsh[pix * 66 + lane + 32];
        float ss = v0 + v1, sq = v0 * v0 + v1 * v1;
        #pragma unroll
        for (int o = 16; o > 0; o >>= 1) {
            ss += __shfl_xor_sync(0xffffffffu, ss, o);
            sq += __shfl_xor_sync(0xffffffffu, sq, o);
        }
        float mu = ss * (1.f / 64.f);
        float rsg = rsqrtf(sq * (1.f / 64.f) - mu * mu + 1e-5f);
        float y0 = (v0 - mu) * rsg * lw2[lane] + lb2[lane];
        float y1 = (v1 - mu) * rsg * lw2[lane + 32] + lb2[lane + 32];
        yshp[pix * 66 + pairpos(lane)] = __uint_as_float(f2tf32(y0));
        yshp[pix * 66 + pairpos(lane + 32)] = __uint_as_float(f2tf32(y1));
    }
    {
        const float4* wsrc = (const float4*)g_FF1p;
        float4* wdst = (float4*)wshp;
        #pragma unroll
        for (int i = 0; i < 5; i++) {
            int idx = i * 256 + tid;
            if (idx < 1056) wdst[idx] = wsrc[idx];
        }
    }
    __syncthreads();

    // ff1 + bias + GELU -> hshp
    {
        float acc[4][4] = {{0}};
        gemm_66(yshp, wshp, mw * 16, nw, g, t4, acc);
        int r0 = mw * 16 + g, r1 = r0 + 8;
        #pragma unroll
        for (int n = 0; n < 4; n++) {
            int col = nw * 32 + n * 8 + 2 * t4;
            float bb0 = b1[col], bb1 = b1[col + 1];
            float h0 = acc[n][0] + bb0, h1 = acc[n][1] + bb1;
            float h2 = acc[n][2] + bb0, h3 = acc[n][3] + bb1;
            h0 = 0.5f * h0 * (1.f + erff(h0 * 0.70710678118654752f));
            h1 = 0.5f * h1 * (1.f + erff(h1 * 0.70710678118654752f));
            h2 = 0.5f * h2 * (1.f + erff(h2 * 0.70710678118654752f));
            h3 = 0.5f * h3 * (1.f + erff(h3 * 0.70710678118654752f));
            hshp[r0 * 66 + pairpos(col)]     = __uint_as_float(f2tf32(h0));
            hshp[r0 * 66 + pairpos(col + 1)] = __uint_as_float(f2tf32(h1));
            hshp[r1 * 66 + pairpos(col)]     = __uint_as_float(f2tf32(h2));
            hshp[r1 * 66 + pairpos(col + 1)] = __uint_as_float(f2tf32(h3));
        }
    }
    __syncthreads();

    // stage ff2 weights
    {
        const float4* wsrc = (const float4*)g_FF2p;
        float4* wdst = (float4*)wshp;
        #pragma unroll
        for (int i = 0; i < 5; i++) {
            int idx = i * 256 + tid;
            if (idx < 1056) wdst[idx] = wsrc[idx];
        }
    }
    __syncthreads();

    // ff2 + bias + residual + ch0 restore -> global
    {
        float acc[4][4] = {{0}};
        gemm_66(hshp, wshp, mw * 16, nw, g, t4, acc);
        int r0 = mw * 16 + g, r1 = r0 + 8;
        int gp0 = (ty0 + (r0 >> 3)) * 64 + tx0 + (r0 & 7);
        int gp1 = (ty0 + (r1 >> 3)) * 64 + tx0 + (r1 & 7);
        size_t b0a = ((size_t)b * NPIX + gp0) * CCH;
        size_t b1a = ((size_t)b * NPIX + gp1) * CCH;
        #pragma unroll
        for (int n = 0; n < 4; n++) {
            int col = nw * 32 + n * 8 + 2 * t4;
            float v00 = acc[n][0] + b2[col]     + tsh[r0 * 66 + col];
            float v01 = acc[n][1] + b2[col + 1] + tsh[r0 * 66 + col + 1];
            float v10 = acc[n][2] + b2[col]     + tsh[r1 * 66 + col];
            float v11 = acc[n][3] + b2[col + 1] + tsh[r1 * 66 + col + 1];
            if (col == 0) { v00 = xprev[b0a]; v10 = xprev[b1a]; }
            xout[b0a + col]     = v00;
            xout[b0a + col + 1] = v01;
            xout[b1a + col]     = v10;
            xout[b1a + col + 1] = v11;
        }
    }
}

extern "C" void kernel_launch(void* const* d_in, const int* in_sizes, int n_in,
                              void* d_out, int out_size) {
    const float* x = (const float*)d_in[0];
    const void* masks = d_in[1];
    const float* p0_w = (const float*)d_in[2];
    const float* p0_b = (const float*)d_in[3];
    const float* p1_w = (const float*)d_in[4];
    const float* p1_b = (const float*)d_in[5];
    const float* fc0_w = (const float*)d_in[6];
    const float* fc0_b = (const float*)d_in[7];
    const float* fc1_w = (const float*)d_in[8];
    const float* n0w = (const float*)d_in[9];
    const float* n0b = (const float*)d_in[10];
    const float* ln1w = (const float*)d_in[11];
    const float* ln1b = (const float*)d_in[12];
    const float* qkvw = (const float*)d_in[13];
    const float* outw = (const float*)d_in[14];
    const float* outb = (const float*)d_in[15];
    const float* ln2w = (const float*)d_in[16];
    const float* ln2b = (const float*)d_in[17];
    const float* ff1w = (const float*)d_in[18];
    const float* ff1b = (const float*)d_in[19];
    const float* ff2w = (const float*)d_in[20];
    const float* ff2b = (const float*)d_in[21];
    float* out = (float*)d_out;

    cudaFuncSetAttribute(k_mega, cudaFuncAttributeMaxDynamicSharedMemorySize, MEGA_SMEM_BYTES);
    cudaFuncSetAttribute(k_attn_ff, cudaFuncAttributeMaxDynamicSharedMemorySize, AF_SMEM_BYTES);

    k_fold<<<288, 256>>>(fc0_w, fc0_b, p0_w, p0_b, p1_w, p1_b);
    k_prepw<<<48, 256>>>(qkvw, fc1_w, outw, ff1w, ff2w);
    k_maskdetect<<<1, 1024>>>((const unsigned char*)masks, 6 * BATCH * NPIX);

    void* sym = nullptr;
    cudaGetSymbolAddress(&sym, g_xbuf);
    float* buf0 = (float*)sym;
    float* buf1 = buf0 + BATCH * NPIX * CCH;

    const float* cur = x;
    for (int s = 0; s < 6; s++) {
        float* stage = (s & 1) ? buf1 : buf0;
        float* nxt = (s == 5) ? out : stage;
        k_mega<<<256, 256, MEGA_SMEM_BYTES>>>(cur, n0w, n0b, masks, s, stage, ln1w, ln1b);
        k_attn_ff<<<512, 256, AF_SMEM_BYTES>>>(stage, cur, outb, ln2w, ln2b,
                                               ff1b, ff2b, nxt);
        cur = nxt;
    }
}

// round 12
// speedup vs baseline: 1.4155x; 1.4155x over previous
#include <cuda_runtime.h>
#include <math.h>
#include <stdint.h>

#define BATCH 8
#define NPIX 4096
#define CCH 64
#define HID 128
#define ATT_SCALE 0.25f

static __device__ float g_Wswz[9 * 128 * 64];    // pre-swizzled tf32 conv weights [tap][o][64]
static __device__ float g_QKVswz[192 * 64];      // pre-swizzled tf32 qkv weights [o][64]
static __device__ float g_FC1swz[64 * 128];      // pre-swizzled tf32 fc1 weights [o][128]
static __device__ float g_OUTp[64 * 66];         // pair-interleaved tf32 weights
static __device__ float g_FF1p[64 * 66];
static __device__ float g_FF2p[64 * 66];
static __device__ float g_beff[HID];
static __device__ float g_xbuf[2][BATCH * NPIX * CCH];
static __device__ float g_hd[BATCH * NPIX * HID];
static __device__ float g_part[512 * 2];
static __device__ float g_q[BATCH * NPIX * CCH];
static __device__ float g_k[BATCH * NPIX * CCH];
static __device__ float g_v[BATCH * NPIX * CCH];
static __device__ int g_maskmode;

__device__ __forceinline__ uint32_t f2tf32(float f) {
    uint32_t u;
    asm("cvt.rna.tf32.f32 %0, %1;" : "=r"(u) : "f"(f));
    return u;
}

__device__ __forceinline__ int swz_pos(int c, int par) {
    int t4 = c & 3, idx = c >> 2;
    int pi = (t4 * 4 + (((idx >> 2) + t4) & 3)) ^ par;
    return pi * 4 + (idx & 3);
}

__device__ __forceinline__ int pairpos(int k) {
    return (k & 56) + ((k & 3) << 1) + ((k >> 2) & 1);
}

__global__ void k_maskdetect(const unsigned char* m, int nbytes) {
    __shared__ int hasBig, hasMis;
    if (threadIdx.x == 0) { hasBig = 0; hasMis = 0; }
    __syncthreads();
    for (int i = threadIdx.x; i < nbytes; i += blockDim.x) {
        unsigned char v = m[i];
        if (v > 1) hasBig = 1;
        else if (v && (i & 3)) hasMis = 1;
    }
    __syncthreads();
    if (threadIdx.x == 0) g_maskmode = (!hasBig && hasMis) ? 1 : 0;
}

__global__ void k_fold(const float* __restrict__ fc0_w, const float* __restrict__ fc0_b,
                       const float* __restrict__ p0_w, const float* __restrict__ p0_b,
                       const float* __restrict__ p1_w, const float* __restrict__ p1_b) {
    int t = blockIdx.x * 256 + threadIdx.x;
    if (t >= HID * 576) return;
    int o = t / 576, k = t - o * 576;
    int tap = k >> 6, c = k & 63;
    const float* f1 = fc0_w + o * 192 + 64;
    const float* f2 = fc0_w + o * 192 + 128;
    float acc = 0.f;
    for (int m = 0; m < 64; m++) {
        acc = fmaf(f1[m], p0_w[(m * 64 + c) * 9 + tap], acc);
        acc = fmaf(f2[m], p1_w[(m * 64 + c) * 9 + tap], acc);
    }
    if (tap == 4) acc += fc0_w[o * 192 + c];
    g_Wswz[(tap * 128 + o) * 64 + swz_pos(c, o & 1)] = __uint_as_float(f2tf32(acc));
    if (k == 0) {
        float b = fc0_b[o];
        for (int m = 0; m < 64; m++) {
            b = fmaf(f1[m], p0_b[m], b);
            b = fmaf(f2[m], p1_b[m], b);
        }
        g_beff[o] = b;
    }
}

__global__ void k_prepw(const float* __restrict__ qkvw, const float* __restrict__ fc1w,
                        const float* __restrict__ outw, const float* __restrict__ ff1w,
                        const float* __restrict__ ff2w) {
    int t = blockIdx.x * 256 + threadIdx.x;
    if (t < 192 * 64) {
        int o = t >> 6, k = t & 63;
        g_QKVswz[o * 64 + swz_pos(k, o & 1)] = __uint_as_float(f2tf32(qkvw[t]));
    }
    if (t < 64 * 128) {
        int o = t >> 7, k = t & 127;
        int half = k >> 6, kk = k & 63;
        g_FC1swz[o * 128 + half * 64 + swz_pos(kk, o & 1)] = __uint_as_float(f2tf32(fc1w[t]));
    }
    if (t < 64 * 64) {
        int c = t >> 6, k = t & 63;
        int p = c * 66 + pairpos(k);
        g_OUTp[p] = __uint_as_float(f2tf32(outw[t]));
        g_FF1p[p] = __uint_as_float(f2tf32(ff1w[t]));
        g_FF2p[p] = __uint_as_float(f2tf32(ff2w[t]));
    }
    if (t < 128) {
        int c = t >> 1, pos = 64 + (t & 1);
        g_OUTp[c * 66 + pos] = 0.f;
        g_FF1p[c * 66 + pos] = 0.f;
        g_FF2p[c * 66 + pos] = 0.f;
    }
}

__device__ __forceinline__ int refl(int v) { return v < 0 ? -v : (v > 63 ? 126 - v : v); }

__device__ __forceinline__ void mma_tf32(float* c, const uint32_t* a, uint32_t b0, uint32_t b1) {
    asm volatile(
        "mma.sync.aligned.m16n8k8.row.col.f32.tf32.tf32.f32 "
        "{%0,%1,%2,%3}, {%4,%5,%6,%7}, {%8,%9}, {%0,%1,%2,%3};"
        : "+f"(c[0]), "+f"(c[1]), "+f"(c[2]), "+f"(c[3])
        : "r"(a[0]), "r"(a[1]), "r"(a[2]), "r"(a[3]), "r"(b0), "r"(b1));
}

// 16px x 32out x K64 per warp on pair-interleaved stride-66 operands
__device__ __forceinline__ void gemm_66(const float* __restrict__ Ap,
                                        const float* __restrict__ Wp,
                                        int rbase, int nw, int g, int t4,
                                        float acc[4][4]) {
    #pragma unroll
    for (int k0 = 0; k0 < 8; k0++) {
        int kb = k0 * 8 + 2 * t4;
        float2 a0 = *(const float2*)&Ap[(rbase + g) * 66 + kb];
        float2 a1 = *(const float2*)&Ap[(rbase + g + 8) * 66 + kb];
        uint32_t a[4] = {__float_as_uint(a0.x), __float_as_uint(a1.x),
                         __float_as_uint(a0.y), __float_as_uint(a1.y)};
        #pragma unroll
        for (int n = 0; n < 4; n++) {
            float2 b = *(const float2*)&Wp[(nw * 32 + n * 8 + g) * 66 + kb];
            mma_tf32(acc[n], a, __float_as_uint(b.x), __float_as_uint(b.y));
        }
    }
}

// ---------- conv: 128px x 64out per block, double-buffered weights, 1 sync/tap ----------
#define XH_FLOATS (264 * 64)
#define WBUF_FLOATS (64 * 64)
#define CONV_SMEM_BYTES ((XH_FLOATS + 2 * WBUF_FLOATS) * 4)   // 100,352 B -> 2 blocks/SM

__global__ void __launch_bounds__(256, 2) k_conv_mma(const float* __restrict__ xin) {
    extern __shared__ float sm[];
    float* Xh = sm;                       // [264][64] swizzled
    float* Wb0 = sm + XH_FLOATS;          // [64][64] swizzled (buffer 0)
    float* Wb1 = Wb0 + WBUF_FLOATS;       // buffer 1
    int tid = threadIdx.x;
    int blk = blockIdx.x;
    int batch = blk >> 6;
    int rem = blk & 63;
    int y0 = (rem >> 1) << 1;             // ypair
    int nhalf = rem & 1;
    const float* xb = xin + (size_t)batch * NPIX * CCH;
    int warp = tid >> 5, lane = tid & 31;
    int g = lane >> 2, t4 = lane & 3;
    int pixBase = (warp >> 1) * 32;       // 4 warps in M
    int nBaseL = (warp & 1) * 32;         // 2 warps in N (local 0..63)

    // stage halo (reflect), tf32 swizzled
    #pragma unroll 2
    for (int i = 0; i < 66; i++) {
        int lin = i * 256 + tid;
        int ch = lin & 63;
        int hp = lin >> 6;
        int hr = hp / 66, hc = hp - hr * 66;
        int gy = refl(y0 + hr - 1), gx = refl(hc - 1);
        float v = xb[(gy * 64 + gx) * CCH + ch];
        Xh[hp * 64 + swz_pos(ch, hp & 1)] = __uint_as_float(f2tf32(v));
    }

    // preload tap 0 weights -> Wb0 (4 float4 per thread)
    const float4* wsrc4 = (const float4*)g_Wswz;
    float4 wreg[4];
    #pragma unroll
    for (int i = 0; i < 4; i++) wreg[i] = wsrc4[nhalf * 1024 + i * 256 + tid];
    {
        float4* wd = (float4*)Wb0;
        #pragma unroll
        for (int i = 0; i < 4; i++) wd[i * 256 + tid] = wreg[i];
    }
    __syncthreads();

    float acc[2][4][4];
    #pragma unroll
    for (int m = 0; m < 2; m++)
        #pragma unroll
        for (int n = 0; n < 4; n++)
            #pragma unroll
            for (int j2 = 0; j2 < 4; j2++) acc[m][n][j2] = 0.f;

    int cur = 0;
    for (int tap = 0; tap < 9; tap++) {
        int dy = tap / 3, dx = tap - dy * 3;
        float* Wcur = cur ? Wb1 : Wb0;
        // prefetch next tap into regs (overlaps with MMA below)
        if (tap < 8) {
            #pragma unroll
            for (int i = 0; i < 4; i++)
                wreg[i] = wsrc4[(tap + 1) * 2048 + nhalf * 1024 + i * 256 + tid];
        }
        #pragma unroll
        for (int j = 0; j < 4; j++) {
            int pibase = t4 * 4 + ((j + t4) & 3);
            float4 av[4];
            #pragma unroll
            for (int r = 0; r < 4; r++) {
                int pr = pixBase + r * 8 + g;
                int hb = ((pr >> 6) + dy) * 66 + (pr & 63) + dx;
                av[r] = *(const float4*)&Xh[hb * 64 + ((pibase ^ (hb & 1)) << 2)];
            }
            uint32_t aH0m0[4] = {__float_as_uint(av[0].x), __float_as_uint(av[1].x),
                                 __float_as_uint(av[0].y), __float_as_uint(av[1].y)};
            uint32_t aH1m0[4] = {__float_as_uint(av[0].z), __float_as_uint(av[1].z),
                                 __float_as_uint(av[0].w), __float_as_uint(av[1].w)};
            uint32_t aH0m1[4] = {__float_as_uint(av[2].x), __float_as_uint(av[3].x),
                                 __float_as_uint(av[2].y), __float_as_uint(av[3].y)};
            uint32_t aH1m1[4] = {__float_as_uint(av[2].z), __float_as_uint(av[3].z),
                                 __float_as_uint(av[2].w), __float_as_uint(av[3].w)};
            #pragma unroll
            for (int n = 0; n < 4; n++) {
                int o = nBaseL + n * 8 + g;
                float4 bv = *(const float4*)&Wcur[o * 64 + ((pibase ^ (o & 1)) << 2)];
                uint32_t b0 = __float_as_uint(bv.x), b1 = __float_as_uint(bv.y);
                uint32_t b2 = __float_as_uint(bv.z), b3 = __float_as_uint(bv.w);
                mma_tf32(acc[0][n], aH0m0, b0, b1);
                mma_tf32(acc[0][n], aH1m0, b2, b3);
                mma_tf32(acc[1][n], aH0m1, b0, b1);
                mma_tf32(acc[1][n], aH1m1, b2, b3);
            }
        }
        // store prefetched weights into the other buffer (its last readers finished
        // at the previous iteration's syncthreads)
        if (tap < 8) {
            float4* wd = (float4*)(cur ? Wb0 : Wb1);
            #pragma unroll
            for (int i = 0; i < 4; i++) wd[i * 256 + tid] = wreg[i];
        }
        __syncthreads();
        cur ^= 1;
    }

    // epilogue: bias + relu + store + LN partial sums
    float s = 0.f, sq = 0.f;
    #pragma unroll
    for (int m = 0; m < 2; m++) {
        int p_lo = pixBase + m * 16 + g;
        int p_hi = p_lo + 8;
        size_t row_lo = ((size_t)batch * NPIX + y0 * 64 + p_lo) * HID;
        size_t row_hi = ((size_t)batch * NPIX + y0 * 64 + p_hi) * HID;
        #pragma unroll
        for (int n = 0; n < 4; n++) {
            int col = nhalf * 64 + nBaseL + n * 8 + 2 * t4;
            float bo0 = g_beff[col], bo1 = g_beff[col + 1];
            float r0 = fmaxf(acc[m][n][0] + bo0, 0.f);
            float r1 = fmaxf(acc[m][n][1] + bo1, 0.f);
            float r2 = fmaxf(acc[m][n][2] + bo0, 0.f);
            float r3 = fmaxf(acc[m][n][3] + bo1, 0.f);
            *(float2*)&g_hd[row_lo + col] = make_float2(r0, r1);
            *(float2*)&g_hd[row_hi + col] = make_float2(r2, r3);
            s += r0 + r1 + r2 + r3;
            sq += r0 * r0 + r1 * r1 + r2 * r2 + r3 * r3;
        }
    }
    float* red = sm;   // reuse (all MMA reads done past final sync)
    red[tid] = s; red[256 + tid] = sq;
    __syncthreads();
    for (int st = 128; st > 0; st >>= 1) {
        if (tid < st) { red[tid] += red[tid + st]; red[256 + tid] += red[256 + tid + st]; }
        __syncthreads();
    }
    if (tid == 0) { g_part[blk * 2] = red[0]; g_part[blk * 2 + 1] = red[256]; }
}

// ---------------- fused fc1 + qkv: 64 px per block (round-10 proven) ----------------
#define FQ_SMEM_BYTES ((16384 + 4096) * 4)

__global__ void __launch_bounds__(256, 2) k_fc1qkv(const float* __restrict__ xin,
                                                   const float* __restrict__ nw,
                                                   const float* __restrict__ nb,
                                                   const void* __restrict__ mask, int s,
                                                   float* __restrict__ xout,
                                                   const float* __restrict__ lw,
                                                   const float* __restrict__ lb) {
    extern __shared__ float sm[];
    float* pool = sm;
    float* xsh = sm + 16384;
    __shared__ float s_mu, s_rs;
    int tid = threadIdx.x;
    int b = blockIdx.x >> 6;
    int p0 = (blockIdx.x & 63) << 6;
    int warp = tid >> 5, lane = tid & 31;
    int g = lane >> 2, t4 = lane & 3;

    float* ysh = pool;
    float* Wsh = pool + 64 * 128;

    if (tid < 32) {
        float ss = g_part[(b * 64 + tid) * 2] + g_part[(b * 64 + 32 + tid) * 2];
        float sq = g_part[(b * 64 + tid) * 2 + 1] + g_part[(b * 64 + 32 + tid) * 2 + 1];
        #pragma unroll
        for (int o = 16; o > 0; o >>= 1) {
            ss += __shfl_xor_sync(0xffffffffu, ss, o);
            sq += __shfl_xor_sync(0xffffffffu, sq, o);
        }
        if (tid == 0) {
            const float inv = 1.f / 524288.f;
            float mu = ss * inv;
            s_mu = mu;
            s_rs = rsqrtf(sq * inv - mu * mu + 1e-5f);
        }
    }
    {
        const float4* wsrc = (const float4*)g_FC1swz;
        float4* wdst = (float4*)Wsh;
        #pragma unroll
        for (int i = 0; i < 8; i++) wdst[i * 256 + tid] = wsrc[i * 256 + tid];
    }
    __syncthreads();
    float mu = s_mu, rs = s_rs;

    #pragma unroll
    for (int i = 0; i < 32; i++) {
        int lin = i * 256 + tid;
        int pix = lin >> 7, kk = lin & 127;
        size_t gi = ((size_t)b * NPIX + p0 + pix) * HID + kk;
        int ii = (p0 + pix) * HID + kk;
        float y = (g_hd[gi] - mu) * rs * nw[ii] + nb[ii];
        int half = kk >> 6, kc = kk & 63;
        ysh[pix * 128 + half * 64 + swz_pos(kc, pix & 1)] = __uint_as_float(f2tf32(y));
    }
    __syncthreads();

    {
        int pixBase = (warp & 1) * 32;
        int oBase = (warp >> 1) * 16;

        float acc[2][2][4];
        #pragma unroll
        for (int m = 0; m < 2; m++)
            #pragma unroll
            for (int n = 0; n < 2; n++)
                #pragma unroll
                for (int j = 0; j < 4; j++) acc[m][n][j] = 0.f;

        #pragma unroll
        for (int half = 0; half < 2; half++) {
            #pragma unroll
            for (int j = 0; j < 4; j++) {
                int pibase = t4 * 4 + ((j + t4) & 3);
                float4 av[4];
                #pragma unroll
                for (int r = 0; r < 4; r++) {
                    int pr = pixBase + r * 8 + g;
                    av[r] = *(const float4*)&ysh[pr * 128 + half * 64 + ((pibase ^ (pr & 1)) << 2)];
                }
                uint32_t aH0m0[4] = {__float_as_uint(av[0].x), __float_as_uint(av[1].x),
                                     __float_as_uint(av[0].y), __float_as_uint(av[1].y)};
                uint32_t aH1m0[4] = {__float_as_uint(av[0].z), __float_as_uint(av[1].z),
                                     __float_as_uint(av[0].w), __float_as_uint(av[1].w)};
                uint32_t aH0m1[4] = {__float_as_uint(av[2].x), __float_as_uint(av[3].x),
                                     __float_as_uint(av[2].y), __float_as_uint(av[3].y)};
                uint32_t aH1m1[4] = {__float_as_uint(av[2].z), __float_as_uint(av[3].z),
                                     __float_as_uint(av[2].w), __float_as_uint(av[3].w)};
                #pragma unroll
                for (int n = 0; n < 2; n++) {
                    int o = oBase + n * 8 + g;
                    float4 bv = *(const float4*)&Wsh[o * 128 + half * 64 + ((pibase ^ (o & 1)) << 2)];
                    uint32_t b0 = __float_as_uint(bv.x), b1 = __float_as_uint(bv.y);
                    uint32_t b2 = __float_as_uint(bv.z), b3 = __float_as_uint(bv.w);
                    mma_tf32(acc[0][n], aH0m0, b0, b1);
                    mma_tf32(acc[0][n], aH1m0, b2, b3);
                    mma_tf32(acc[1][n], aH0m1, b0, b1);
                    mma_tf32(acc[1][n], aH1m1, b2, b3);
                }
            }
        }

        int mode = g_maskmode;
        #pragma unroll
        for (int m = 0; m < 2; m++) {
            int p_lo = pixBase + m * 16 + g;
            int p_hi = p_lo + 8;
            size_t gplo = (size_t)b * NPIX + p0 + p_lo;
            size_t gphi = (size_t)b * NPIX + p0 + p_hi;
            size_t milo = (size_t)s * 32768 + gplo;
            size_t mihi = (size_t)s * 32768 + gphi;
            float mvlo, mvhi;
            if (mode) {
                mvlo = ((const unsigned char*)mask)[milo] ? 1.f : 0.f;
                mvhi = ((const unsigned char*)mask)[mihi] ? 1.f : 0.f;
            } else {
                mvlo = ((const unsigned int*)mask)[milo] ? 1.f : 0.f;
                mvhi = ((const unsigned int*)mask)[mihi] ? 1.f : 0.f;
            }
            #pragma unroll
            for (int n = 0; n < 2; n++) {
                int col = oBase + n * 8 + 2 * t4;
                float2 x0 = *(const float2*)&xin[gplo * CCH + col];
                float2 x1 = *(const float2*)&xin[gphi * CCH + col];
                float2 o0 = make_float2(x0.x + acc[m][n][0] * mvlo, x0.y + acc[m][n][1] * mvlo);
                float2 o1 = make_float2(x1.x + acc[m][n][2] * mvhi, x1.y + acc[m][n][3] * mvhi);
                *(float2*)&xout[gplo * CCH + col] = o0;
                *(float2*)&xout[gphi * CCH + col] = o1;
                *(float2*)&xsh[p_lo * 64 + col] = o0;
                *(float2*)&xsh[p_hi * 64 + col] = o1;
            }
        }
    }
    __syncthreads();

    float* ysh2 = pool;
    float* WshQ = pool + 64 * 64;

    #pragma unroll
    for (int k = 0; k < 8; k++) {
        int pix = warp * 8 + k;
        float v0 = xsh[pix * 64 + lane], v1 = xsh[pix * 64 + lane + 32];
        float ss = v0 + v1, sq = v0 * v0 + v1 * v1;
        #pragma unroll
        for (int o = 16; o > 0; o >>= 1) {
            ss += __shfl_xor_sync(0xffffffffu, ss, o);
            sq += __shfl_xor_sync(0xffffffffu, sq, o);
        }
        float mu2 = ss * (1.f / 64.f);
        float rsg = rsqrtf(sq * (1.f / 64.f) - mu2 * mu2 + 1e-5f);
        float y0 = (v0 - mu2) * rsg * lw[lane] + lb[lane];
        float y1 = (v1 - mu2) * rsg * lw[lane + 32] + lb[lane + 32];
        ysh2[pix * 64 + swz_pos(lane, pix & 1)] = __uint_as_float(f2tf32(y0));
        ysh2[pix * 64 + swz_pos(lane + 32, pix & 1)] = __uint_as_float(f2tf32(y1));
    }
    {
        const float4* wsrc = (const float4*)g_QKVswz;
        float4* wdst = (float4*)WshQ;
        #pragma unroll
        for (int i = 0; i < 12; i++) wdst[i * 256 + tid] = wsrc[i * 256 + tid];
    }
    __syncthreads();

    {
        int pixBase = (warp & 1) * 32;
        int oBase = (warp >> 1) * 48;

        float acc[2][6][4];
        #pragma unroll
        for (int m = 0; m < 2; m++)
            #pragma unroll
            for (int n = 0; n < 6; n++)
                #pragma unroll
                for (int j = 0; j < 4; j++) acc[m][n][j] = 0.f;

        #pragma unroll
        for (int j = 0; j < 4; j++) {
            int pibase = t4 * 4 + ((j + t4) & 3);
            float4 av[4];
            #pragma unroll
            for (int r = 0; r < 4; r++) {
                int pr = pixBase + r * 8 + g;
                av[r] = *(const float4*)&ysh2[pr * 64 + ((pibase ^ (pr & 1)) << 2)];
            }
            uint32_t aH0m0[4] = {__float_as_uint(av[0].x), __float_as_uint(av[1].x),
                                 __float_as_uint(av[0].y), __float_as_uint(av[1].y)};
            uint32_t aH1m0[4] = {__float_as_uint(av[0].z), __float_as_uint(av[1].z),
                                 __float_as_uint(av[0].w), __float_as_uint(av[1].w)};
            uint32_t aH0m1[4] = {__float_as_uint(av[2].x), __float_as_uint(av[3].x),
                                 __float_as_uint(av[2].y), __float_as_uint(av[3].y)};
            uint32_t aH1m1[4] = {__float_as_uint(av[2].z), __float_as_uint(av[3].z),
                                 __float_as_uint(av[2].w), __float_as_uint(av[3].w)};
            #pragma unroll
            for (int n = 0; n < 6; n++) {
                int o = oBase + n * 8 + g;
                float4 bv = *(const float4*)&WshQ[o * 64 + ((pibase ^ (o & 1)) << 2)];
                uint32_t b0 = __float_as_uint(bv.x), b1 = __float_as_uint(bv.y);
                uint32_t b2 = __float_as_uint(bv.z), b3 = __float_as_uint(bv.w);
                mma_tf32(acc[0][n], aH0m0, b0, b1);
                mma_tf32(acc[0][n], aH1m0, b2, b3);
                mma_tf32(acc[1][n], aH0m1, b0, b1);
                mma_tf32(acc[1][n], aH1m1, b2, b3);
            }
        }

        #pragma unroll
        for (int m = 0; m < 2; m++) {
            int p_lo = pixBase + m * 16 + g;
            int p_hi = p_lo + 8;
            size_t gplo = (size_t)b * NPIX + p0 + p_lo;
            size_t gphi = (size_t)b * NPIX + p0 + p_hi;
            #pragma unroll
            for (int n = 0; n < 6; n++) {
                int col = oBase + n * 8 + 2 * t4;
                int region = col >> 6;
                int c = col & 63;
                float* dst = (region == 0) ? g_q : (region == 1) ? g_k : g_v;
                *(float2*)&dst[gplo * CCH + c] = make_float2(acc[m][n][0], acc[m][n][1]);
                *(float2*)&dst[gphi * CCH + c] = make_float2(acc[m][n][2], acc[m][n][3]);
            }
        }
    }
}

// ---------------- fused attn + out-proj + ff with MMA GEMMs: 32 px per block (round-10) ----------------
#define AF_SMEM_BYTES (16256 * 4)

__global__ void __launch_bounds__(128) k_attn_ff(const float* __restrict__ xn,
                                                 const float* __restrict__ xprev,
                                                 const float* __restrict__ outb,
                                                 const float* __restrict__ lw2,
                                                 const float* __restrict__ lb2,
                                                 const float* __restrict__ b1,
                                                 const float* __restrict__ b2,
                                                 float* __restrict__ xout) {
    extern __shared__ float sm[];
    float* ksh = sm;
    float* vsh = sm + 3904;
    float* wshp = sm;
    float* oshp = sm + 7808;
    float* tsh = oshp + 2112;
    float* yshp = tsh + 2112;
    float* hshp = yshp + 2112;
    int tid = threadIdx.x;
    int b = blockIdx.x >> 7;
    int tile = blockIdx.x & 127;
    int tx0 = (tile & 7) << 3;
    int ty0 = (tile >> 3) << 2;
    int warp = tid >> 5, lane = tid & 31;
    int g = lane >> 2, t4 = lane & 3;
    int mw = warp & 1, nw = warp >> 1;

    #pragma unroll
    for (int i = 0; i < 30; i++) {
        int lin = tid + i * 128;
        int pos = lin >> 6, ch = lin & 63;
        int hy = pos / 10, hx = pos - hy * 10;
        int gy = ty0 + hy - 1, gx = tx0 + hx - 1;
        float kv = 0.f, vv = 0.f;
        if ((unsigned)gy < 64u && (unsigned)gx < 64u) {
            size_t a = ((size_t)b * NPIX + gy * 64 + gx) * CCH + ch;
            kv = g_k[a]; vv = g_v[a];
        }
        ksh[ch * 61 + pos] = kv;
        vsh[ch * 61 + pos] = vv;
    }
    __syncthreads();

    {
        int head = warp, lp = lane;
        int py = lp >> 3, px = lp & 7;
        int gy = ty0 + py, gx = tx0 + px;
        size_t qbase = ((size_t)b * NPIX + gy * 64 + gx) * CCH + head * 16;
        float q[16];
        #pragma unroll
        for (int i = 0; i < 4; i++) {
            float4 t4v = *(const float4*)&g_q[qbase + i * 4];
            q[i * 4] = t4v.x; q[i * 4 + 1] = t4v.y; q[i * 4 + 2] = t4v.z; q[i * 4 + 3] = t4v.w;
        }
        float lg[9];
        #pragma unroll
        for (int t = 0; t < 9; t++) {
            int pos = (py + t / 3) * 10 + px + t % 3;
            float d = 0.f;
            #pragma unroll
            for (int i = 0; i < 16; i++) d = fmaf(q[i], ksh[(head * 16 + i) * 61 + pos], d);
            lg[t] = d * ATT_SCALE;
        }
        float m = lg[0];
        #pragma unroll
        for (int t = 1; t < 9; t++) m = fmaxf(m, lg[t]);
        float e[9], ssum = 0.f;
        #pragma unroll
        for (int t = 0; t < 9; t++) { e[t] = __expf(lg[t] - m); ssum += e[t]; }
        float inv = 1.f / ssum;
        float o[16] = {};
        #pragma unroll
        for (int t = 0; t < 9; t++) {
            int pos = (py + t / 3) * 10 + px + t % 3;
            float a = e[t] * inv;
            #pragma unroll
            for (int i = 0; i < 16; i++) o[i] = fmaf(a, vsh[(head * 16 + i) * 61 + pos], o[i]);
        }
        #pragma unroll
        for (int i = 0; i < 16; i++)
            oshp[lp * 66 + pairpos(head * 16 + i)] = __uint_as_float(f2tf32(o[i]));
    }
    __syncthreads();

    {
        const float4* wsrc = (const float4*)g_OUTp;
        float4* wdst = (float4*)wshp;
        #pragma unroll
        for (int i = 0; i < 9; i++) {
            int idx = i * 128 + tid;
            if (idx < 1056) wdst[idx] = wsrc[idx];
        }
    }
    __syncthreads();

    {
        float acc[4][4] = {{0}};
        gemm_66(oshp, wshp, mw * 16, nw, g, t4, acc);
        int r0 = mw * 16 + g, r1 = r0 + 8;
        int gp0 = (ty0 + (r0 >> 3)) * 64 + tx0 + (r0 & 7);
        int gp1 = (ty0 + (r1 >> 3)) * 64 + tx0 + (r1 & 7);
        size_t b0a = ((size_t)b * NPIX + gp0) * CCH;
        size_t b1a = ((size_t)b * NPIX + gp1) * CCH;
        #pragma unroll
        for (int n = 0; n < 4; n++) {
            int col = nw * 32 + n * 8 + 2 * t4;
            tsh[r0 * 66 + col]     = acc[n][0] + outb[col]     + xn[b0a + col];
            tsh[r0 * 66 + col + 1] = acc[n][1] + outb[col + 1] + xn[b0a + col + 1];
            tsh[r1 * 66 + col]     = acc[n][2] + outb[col]     + xn[b1a + col];
            tsh[r1 * 66 + col + 1] = acc[n][3] + outb[col + 1] + xn[b1a + col + 1];
        }
    }
    __syncthreads();

    #pragma unroll
    for (int k = 0; k < 8; k++) {
        int pix = warp * 8 + k;
        float v0 = tsh[pix * 66 + lane], v1 = tsh[pix * 66 + lane + 32];
        float ss = v0 + v1, sq = v0 * v0 + v1 * v1;
        #pragma unroll
        for (int o = 16; o > 0; o >>= 1) {
            ss += __shfl_xor_sync(0xffffffffu, ss, o);
            sq += __shfl_xor_sync(0xffffffffu, sq, o);
        }
        float mu = ss * (1.f / 64.f);
        float rsg = rsqrtf(sq * (1.f / 64.f) - mu * mu + 1e-5f);
        float y0 = (v0 - mu) * rsg * lw2[lane] + lb2[lane];
        float y1 = (v1 - mu) * rsg * lw2[lane + 32] + lb2[lane + 32];
        yshp[pix * 66 + pairpos(lane)] = __uint_as_float(f2tf32(y0));
        yshp[pix * 66 + pairpos(lane + 32)] = __uint_as_float(f2tf32(y1));
    }
    {
        const float4* wsrc = (const float4*)g_FF1p;
        float4* wdst = (float4*)wshp;
        #pragma unroll
        for (int i = 0; i < 9; i++) {
            int idx = i * 128 + tid;
            if (idx < 1056) wdst[idx] = wsrc[idx];
        }
    }
    __syncthreads();

    {
        float acc[4][4] = {{0}};
        gemm_66(yshp, wshp, mw * 16, nw, g, t4, acc);
        int r0 = mw * 16 + g, r1 = r0 + 8;
        #pragma unroll
        for (int n = 0; n < 4; n++) {
            int col = nw * 32 + n * 8 + 2 * t4;
            float bb0 = b1[col], bb1 = b1[col + 1];
            float h0 = acc[n][0] + bb0, h1 = acc[n][1] + bb1;
            float h2 = acc[n][2] + bb0, h3 = acc[n][3] + bb1;
            h0 = 0.5f * h0 * (1.f + erff(h0 * 0.70710678118654752f));
            h1 = 0.5f * h1 * (1.f + erff(h1 * 0.70710678118654752f));
            h2 = 0.5f * h2 * (1.f + erff(h2 * 0.70710678118654752f));
            h3 = 0.5f * h3 * (1.f + erff(h3 * 0.70710678118654752f));
            hshp[r0 * 66 + pairpos(col)]     = __uint_as_float(f2tf32(h0));
            hshp[r0 * 66 + pairpos(col + 1)] = __uint_as_float(f2tf32(h1));
            hshp[r1 * 66 + pairpos(col)]     = __uint_as_float(f2tf32(h2));
            hshp[r1 * 66 + pairpos(col + 1)] = __uint_as_float(f2tf32(h3));
        }
    }
    __syncthreads();

    {
        const float4* wsrc = (const float4*)g_FF2p;
        float4* wdst = (float4*)wshp;
        #pragma unroll
        for (int i = 0; i < 9; i++) {
            int idx = i * 128 + tid;
            if (idx < 1056) wdst[idx] = wsrc[idx];
        }
    }
    __syncthreads();

    {
        float acc[4][4] = {{0}};
        gemm_66(hshp, wshp, mw * 16, nw, g, t4, acc);
        int r0 = mw * 16 + g, r1 = r0 + 8;
        int gp0 = (ty0 + (r0 >> 3)) * 64 + tx0 + (r0 & 7);
        int gp1 = (ty0 + (r1 >> 3)) * 64 + tx0 + (r1 & 7);
        size_t b0a = ((size_t)b * NPIX + gp0) * CCH;
        size_t b1a = ((size_t)b * NPIX + gp1) * CCH;
        #pragma unroll
        for (int n = 0; n < 4; n++) {
            int col = nw * 32 + n * 8 + 2 * t4;
            float v00 = acc[n][0] + b2[col]     + tsh[r0 * 66 + col];
            float v01 = acc[n][1] + b2[col + 1] + tsh[r0 * 66 + col + 1];
            float v10 = acc[n][2] + b2[col]     + tsh[r1 * 66 + col];
            float v11 = acc[n][3] + b2[col + 1] + tsh[r1 * 66 + col + 1];
            if (col == 0) { v00 = xprev[b0a]; v10 = xprev[b1a]; }
            xout[b0a + col]     = v00;
            xout[b0a + col + 1] = v01;
            xout[b1a + col]     = v10;
            xout[b1a + col + 1] = v11;
        }
    }
}

extern "C" void kernel_launch(void* const* d_in, const int* in_sizes, int n_in,
                              void* d_out, int out_size) {
    const float* x = (const float*)d_in[0];
    const void* masks = d_in[1];
    const float* p0_w = (const float*)d_in[2];
    const float* p0_b = (const float*)d_in[3];
    const float* p1_w = (const float*)d_in[4];
    const float* p1_b = (const float*)d_in[5];
    const float* fc0_w = (const float*)d_in[6];
    const float* fc0_b = (const float*)d_in[7];
    const float* fc1_w = (const float*)d_in[8];
    const float* n0w = (const float*)d_in[9];
    const float* n0b = (const float*)d_in[10];
    const float* ln1w = (const float*)d_in[11];
    const float* ln1b = (const float*)d_in[12];
    const float* qkvw = (const float*)d_in[13];
    const float* outw = (const float*)d_in[14];
    const float* outb = (const float*)d_in[15];
    const float* ln2w = (const float*)d_in[16];
    const float* ln2b = (const float*)d_in[17];
    const float* ff1w = (const float*)d_in[18];
    const float* ff1b = (const float*)d_in[19];
    const float* ff2w = (const float*)d_in[20];
    const float* ff2b = (const float*)d_in[21];
    float* out = (float*)d_out;

    cudaFuncSetAttribute(k_conv_mma, cudaFuncAttributeMaxDynamicSharedMemorySize, CONV_SMEM_BYTES);
    cudaFuncSetAttribute(k_fc1qkv, cudaFuncAttributeMaxDynamicSharedMemorySize, FQ_SMEM_BYTES);
    cudaFuncSetAttribute(k_attn_ff, cudaFuncAttributeMaxDynamicSharedMemorySize, AF_SMEM_BYTES);

    k_fold<<<288, 256>>>(fc0_w, fc0_b, p0_w, p0_b, p1_w, p1_b);
    k_prepw<<<48, 256>>>(qkvw, fc1_w, outw, ff1w, ff2w);
    k_maskdetect<<<1, 1024>>>((const unsigned char*)masks, 6 * BATCH * NPIX);

    void* sym = nullptr;
    cudaGetSymbolAddress(&sym, g_xbuf);
    float* buf0 = (float*)sym;
    float* buf1 = buf0 + BATCH * NPIX * CCH;

    const float* cur = x;
    for (int s = 0; s < 6; s++) {
        float* stage = (s & 1) ? buf1 : buf0;
        float* nxt = (s == 5) ? out : stage;
        k_conv_mma<<<512, 256, CONV_SMEM_BYTES>>>(cur);
        k_fc1qkv<<<512, 256, FQ_SMEM_BYTES>>>(cur, n0w, n0b, masks, s, stage, ln1w, ln1b);
        k_attn_ff<<<1024, 128, AF_SMEM_BYTES>>>(stage, cur, outb, ln2w, ln2b,
                                                ff1b, ff2b, nxt);
        cur = nxt;
    }
}

// round 13
// speedup vs baseline: 1.4641x; 1.0343x over previous
#include <cuda_runtime.h>
#include <math.h>
#include <stdint.h>

#define BATCH 8
#define NPIX 4096
#define CCH 64
#define HID 128
#define ATT_SCALE 0.25f

static __device__ float g_Wswz[9 * 128 * 64];    // pre-swizzled tf32 conv weights [tap][o][64]
static __device__ float g_QKVswz[192 * 64];      // pre-swizzled tf32 qkv weights [o][64]
static __device__ float g_FC1swz[64 * 128];      // pre-swizzled tf32 fc1 weights [o][128]
static __device__ float g_OUTp[64 * 66];         // pair-interleaved tf32 weights
static __device__ float g_FF1p[64 * 66];
static __device__ float g_FF2p[64 * 66];
static __device__ float g_beff[HID];
static __device__ float g_xbuf[2][BATCH * NPIX * CCH];
static __device__ float g_hd[BATCH * NPIX * HID];
static __device__ float g_part[256 * 2];
static __device__ float g_q[BATCH * NPIX * CCH];
static __device__ float g_k[BATCH * NPIX * CCH];
static __device__ float g_v[BATCH * NPIX * CCH];
static __device__ int g_maskmode;

__device__ __forceinline__ uint32_t f2tf32(float f) {
    uint32_t u;
    asm("cvt.rna.tf32.f32 %0, %1;" : "=r"(u) : "f"(f));
    return u;
}

__device__ __forceinline__ int swz_pos(int c, int par) {
    int t4 = c & 3, idx = c >> 2;
    int pi = (t4 * 4 + (((idx >> 2) + t4) & 3)) ^ par;
    return pi * 4 + (idx & 3);
}

__device__ __forceinline__ int pairpos(int k) {
    return (k & 56) + ((k & 3) << 1) + ((k >> 2) & 1);
}

__global__ void k_maskdetect(const unsigned char* m, int nbytes) {
    __shared__ int hasBig, hasMis;
    if (threadIdx.x == 0) { hasBig = 0; hasMis = 0; }
    __syncthreads();
    for (int i = threadIdx.x; i < nbytes; i += blockDim.x) {
        unsigned char v = m[i];
        if (v > 1) hasBig = 1;
        else if (v && (i & 3)) hasMis = 1;
    }
    __syncthreads();
    if (threadIdx.x == 0) g_maskmode = (!hasBig && hasMis) ? 1 : 0;
}

__global__ void k_fold(const float* __restrict__ fc0_w, const float* __restrict__ fc0_b,
                       const float* __restrict__ p0_w, const float* __restrict__ p0_b,
                       const float* __restrict__ p1_w, const float* __restrict__ p1_b) {
    int t = blockIdx.x * 256 + threadIdx.x;
    if (t >= HID * 576) return;
    int o = t / 576, k = t - o * 576;
    int tap = k >> 6, c = k & 63;
    const float* f1 = fc0_w + o * 192 + 64;
    const float* f2 = fc0_w + o * 192 + 128;
    float acc = 0.f;
    for (int m = 0; m < 64; m++) {
        acc = fmaf(f1[m], p0_w[(m * 64 + c) * 9 + tap], acc);
        acc = fmaf(f2[m], p1_w[(m * 64 + c) * 9 + tap], acc);
    }
    if (tap == 4) acc += fc0_w[o * 192 + c];
    g_Wswz[(tap * 128 + o) * 64 + swz_pos(c, o & 1)] = __uint_as_float(f2tf32(acc));
    if (k == 0) {
        float b = fc0_b[o];
        for (int m = 0; m < 64; m++) {
            b = fmaf(f1[m], p0_b[m], b);
            b = fmaf(f2[m], p1_b[m], b);
        }
        g_beff[o] = b;
    }
}

__global__ void k_prepw(const float* __restrict__ qkvw, const float* __restrict__ fc1w,
                        const float* __restrict__ outw, const float* __restrict__ ff1w,
                        const float* __restrict__ ff2w) {
    int t = blockIdx.x * 256 + threadIdx.x;
    if (t < 192 * 64) {
        int o = t >> 6, k = t & 63;
        g_QKVswz[o * 64 + swz_pos(k, o & 1)] = __uint_as_float(f2tf32(qkvw[t]));
    }
    if (t < 64 * 128) {
        int o = t >> 7, k = t & 127;
        int half = k >> 6, kk = k & 63;
        g_FC1swz[o * 128 + half * 64 + swz_pos(kk, o & 1)] = __uint_as_float(f2tf32(fc1w[t]));
    }
    if (t < 64 * 64) {
        int c = t >> 6, k = t & 63;
        int p = c * 66 + pairpos(k);
        g_OUTp[p] = __uint_as_float(f2tf32(outw[t]));
        g_FF1p[p] = __uint_as_float(f2tf32(ff1w[t]));
        g_FF2p[p] = __uint_as_float(f2tf32(ff2w[t]));
    }
    if (t < 128) {
        int c = t >> 1, pos = 64 + (t & 1);
        g_OUTp[c * 66 + pos] = 0.f;
        g_FF1p[c * 66 + pos] = 0.f;
        g_FF2p[c * 66 + pos] = 0.f;
    }
}

__device__ __forceinline__ int refl(int v) { return v < 0 ? -v : (v > 63 ? 126 - v : v); }

__device__ __forceinline__ void mma_tf32(float* c, const uint32_t* a, uint32_t b0, uint32_t b1) {
    asm volatile(
        "mma.sync.aligned.m16n8k8.row.col.f32.tf32.tf32.f32 "
        "{%0,%1,%2,%3}, {%4,%5,%6,%7}, {%8,%9}, {%0,%1,%2,%3};"
        : "+f"(c[0]), "+f"(c[1]), "+f"(c[2]), "+f"(c[3])
        : "r"(a[0]), "r"(a[1]), "r"(a[2]), "r"(a[3]), "r"(b0), "r"(b1));
}

// 16px x 32out x K64 per warp on pair-interleaved stride-66 operands
__device__ __forceinline__ void gemm_66(const float* __restrict__ Ap,
                                        const float* __restrict__ Wp,
                                        int rbase, int nw, int g, int t4,
                                        float acc[4][4]) {
    #pragma unroll
    for (int k0 = 0; k0 < 8; k0++) {
        int kb = k0 * 8 + 2 * t4;
        float2 a0 = *(const float2*)&Ap[(rbase + g) * 66 + kb];
        float2 a1 = *(const float2*)&Ap[(rbase + g + 8) * 66 + kb];
        uint32_t a[4] = {__float_as_uint(a0.x), __float_as_uint(a1.x),
                         __float_as_uint(a0.y), __float_as_uint(a1.y)};
        #pragma unroll
        for (int n = 0; n < 4; n++) {
            float2 b = *(const float2*)&Wp[(nw * 32 + n * 8 + g) * 66 + kb];
            mma_tf32(acc[n], a, __float_as_uint(b.x), __float_as_uint(b.y));
        }
    }
}

// ---------------- tensor-core conv: 128 pix x 128 out per block (round-10 proven) ----------------
#define XH_FLOATS (264 * 64)
#define W_FLOATS (128 * 64)
#define CONV_SMEM_BYTES ((XH_FLOATS + W_FLOATS) * 4)

__global__ void __launch_bounds__(256, 2) k_conv_mma(const float* __restrict__ xin) {
    extern __shared__ float sm[];
    float* Xh = sm;
    float* Wsh = sm + XH_FLOATS;
    int tid = threadIdx.x;
    int batch = blockIdx.x >> 5;
    int y0 = (blockIdx.x & 31) << 1;
    const float* xb = xin + (size_t)batch * NPIX * CCH;

    #pragma unroll 2
    for (int i = 0; i < 66; i++) {
        int lin = i * 256 + tid;
        int ch = lin & 63;
        int hp = lin >> 6;
        int hr = hp / 66, hc = hp - hr * 66;
        int gy = refl(y0 + hr - 1), gx = refl(hc - 1);
        float v = xb[(gy * 64 + gx) * CCH + ch];
        Xh[hp * 64 + swz_pos(ch, hp & 1)] = __uint_as_float(f2tf32(v));
    }

    int warp = tid >> 5, lane = tid & 31;
    int g = lane >> 2, t4 = lane & 3;
    int pixBase = (warp >> 1) * 32;
    int nBase = (warp & 1) * 64;

    float acc[2][8][4];
    #pragma unroll
    for (int m = 0; m < 2; m++)
        #pragma unroll
        for (int n = 0; n < 8; n++)
            #pragma unroll
            for (int j2 = 0; j2 < 4; j2++) acc[m][n][j2] = 0.f;

    for (int tap = 0; tap < 9; tap++) {
        int dy = tap / 3, dx = tap - dy * 3;
        __syncthreads();
        {
            const float4* wsrc = (const float4*)(g_Wswz + tap * (128 * 64));
            float4* wdst = (float4*)Wsh;
            #pragma unroll
            for (int i = 0; i < 8; i++) wdst[i * 256 + tid] = wsrc[i * 256 + tid];
        }
        __syncthreads();

        #pragma unroll
        for (int j = 0; j < 4; j++) {
            int pibase = t4 * 4 + ((j + t4) & 3);
            float4 av[4];
            #pragma unroll
            for (int r = 0; r < 4; r++) {
                int pr = pixBase + r * 8 + g;
                int hb = ((pr >> 6) + dy) * 66 + (pr & 63) + dx;
                av[r] = *(const float4*)&Xh[hb * 64 + ((pibase ^ (hb & 1)) << 2)];
            }
            uint32_t aH0m0[4] = {__float_as_uint(av[0].x), __float_as_uint(av[1].x),
                                 __float_as_uint(av[0].y), __float_as_uint(av[1].y)};
            uint32_t aH1m0[4] = {__float_as_uint(av[0].z), __float_as_uint(av[1].z),
                                 __float_as_uint(av[0].w), __float_as_uint(av[1].w)};
            uint32_t aH0m1[4] = {__float_as_uint(av[2].x), __float_as_uint(av[3].x),
                                 __float_as_uint(av[2].y), __float_as_uint(av[3].y)};
            uint32_t aH1m1[4] = {__float_as_uint(av[2].z), __float_as_uint(av[3].z),
                                 __float_as_uint(av[2].w), __float_as_uint(av[3].w)};
            #pragma unroll
            for (int n = 0; n < 8; n++) {
                int o = nBase + n * 8 + g;
                float4 bv = *(const float4*)&Wsh[o * 64 + ((pibase ^ (o & 1)) << 2)];
                uint32_t b0 = __float_as_uint(bv.x), b1 = __float_as_uint(bv.y);
                uint32_t b2 = __float_as_uint(bv.z), b3 = __float_as_uint(bv.w);
                mma_tf32(acc[0][n], aH0m0, b0, b1);
                mma_tf32(acc[0][n], aH1m0, b2, b3);
                mma_tf32(acc[1][n], aH0m1, b0, b1);
                mma_tf32(acc[1][n], aH1m1, b2, b3);
            }
        }
    }
    __syncthreads();

    float s = 0.f, sq = 0.f;
    #pragma unroll
    for (int m = 0; m < 2; m++) {
        int p_lo = pixBase + m * 16 + g;
        int p_hi = p_lo + 8;
        size_t row_lo = ((size_t)batch * NPIX + y0 * 64 + p_lo) * HID;
        size_t row_hi = ((size_t)batch * NPIX + y0 * 64 + p_hi) * HID;
        #pragma unroll
        for (int n = 0; n < 8; n++) {
            int col = nBase + n * 8 + 2 * t4;
            float bo0 = g_beff[col], bo1 = g_beff[col + 1];
            float r0 = fmaxf(acc[m][n][0] + bo0, 0.f);
            float r1 = fmaxf(acc[m][n][1] + bo1, 0.f);
            float r2 = fmaxf(acc[m][n][2] + bo0, 0.f);
            float r3 = fmaxf(acc[m][n][3] + bo1, 0.f);
            *(float2*)&g_hd[row_lo + col] = make_float2(r0, r1);
            *(float2*)&g_hd[row_hi + col] = make_float2(r2, r3);
            s += r0 + r1 + r2 + r3;
            sq += r0 * r0 + r1 * r1 + r2 * r2 + r3 * r3;
        }
    }
    float* red = sm;
    red[tid] = s; red[256 + tid] = sq;
    __syncthreads();
    for (int st = 128; st > 0; st >>= 1) {
        if (tid < st) { red[tid] += red[tid + st]; red[256 + tid] += red[256 + tid + st]; }
        __syncthreads();
    }
    if (tid == 0) { g_part[blockIdx.x * 2] = red[0]; g_part[blockIdx.x * 2 + 1] = red[256]; }
}

// ---------------- fused fc1 + qkv: 64 px per block (round-10 proven) ----------------
#define FQ_SMEM_BYTES ((16384 + 4096) * 4)

__global__ void __launch_bounds__(256, 2) k_fc1qkv(const float* __restrict__ xin,
                                                   const float* __restrict__ nw,
                                                   const float* __restrict__ nb,
                                                   const void* __restrict__ mask, int s,
                                                   float* __restrict__ xout,
                                                   const float* __restrict__ lw,
                                                   const float* __restrict__ lb) {
    extern __shared__ float sm[];
    float* pool = sm;
    float* xsh = sm + 16384;
    __shared__ float s_mu, s_rs;
    int tid = threadIdx.x;
    int b = blockIdx.x >> 6;
    int p0 = (blockIdx.x & 63) << 6;
    int warp = tid >> 5, lane = tid & 31;
    int g = lane >> 2, t4 = lane & 3;

    float* ysh = pool;
    float* Wsh = pool + 64 * 128;

    if (tid < 32) {
        float ss = g_part[(b * 32 + tid) * 2];
        float sq = g_part[(b * 32 + tid) * 2 + 1];
        #pragma unroll
        for (int o = 16; o > 0; o >>= 1) {
            ss += __shfl_xor_sync(0xffffffffu, ss, o);
            sq += __shfl_xor_sync(0xffffffffu, sq, o);
        }
        if (tid == 0) {
            const float inv = 1.f / 524288.f;
            float mu = ss * inv;
            s_mu = mu;
            s_rs = rsqrtf(sq * inv - mu * mu + 1e-5f);
        }
    }
    {
        const float4* wsrc = (const float4*)g_FC1swz;
        float4* wdst = (float4*)Wsh;
        #pragma unroll
        for (int i = 0; i < 8; i++) wdst[i * 256 + tid] = wsrc[i * 256 + tid];
    }
    __syncthreads();
    float mu = s_mu, rs = s_rs;

    #pragma unroll
    for (int i = 0; i < 32; i++) {
        int lin = i * 256 + tid;
        int pix = lin >> 7, kk = lin & 127;
        size_t gi = ((size_t)b * NPIX + p0 + pix) * HID + kk;
        int ii = (p0 + pix) * HID + kk;
        float y = (g_hd[gi] - mu) * rs * nw[ii] + nb[ii];
        int half = kk >> 6, kc = kk & 63;
        ysh[pix * 128 + half * 64 + swz_pos(kc, pix & 1)] = __uint_as_float(f2tf32(y));
    }
    __syncthreads();

    {
        int pixBase = (warp & 1) * 32;
        int oBase = (warp >> 1) * 16;

        float acc[2][2][4];
        #pragma unroll
        for (int m = 0; m < 2; m++)
            #pragma unroll
            for (int n = 0; n < 2; n++)
                #pragma unroll
                for (int j = 0; j < 4; j++) acc[m][n][j] = 0.f;

        #pragma unroll
        for (int half = 0; half < 2; half++) {
            #pragma unroll
            for (int j = 0; j < 4; j++) {
                int pibase = t4 * 4 + ((j + t4) & 3);
                float4 av[4];
                #pragma unroll
                for (int r = 0; r < 4; r++) {
                    int pr = pixBase + r * 8 + g;
                    av[r] = *(const float4*)&ysh[pr * 128 + half * 64 + ((pibase ^ (pr & 1)) << 2)];
                }
                uint32_t aH0m0[4] = {__float_as_uint(av[0].x), __float_as_uint(av[1].x),
                                     __float_as_uint(av[0].y), __float_as_uint(av[1].y)};
                uint32_t aH1m0[4] = {__float_as_uint(av[0].z), __float_as_uint(av[1].z),
                                     __float_as_uint(av[0].w), __float_as_uint(av[1].w)};
                uint32_t aH0m1[4] = {__float_as_uint(av[2].x), __float_as_uint(av[3].x),
                                     __float_as_uint(av[2].y), __float_as_uint(av[3].y)};
                uint32_t aH1m1[4] = {__float_as_uint(av[2].z), __float_as_uint(av[3].z),
                                     __float_as_uint(av[2].w), __float_as_uint(av[3].w)};
                #pragma unroll
                for (int n = 0; n < 2; n++) {
                    int o = oBase + n * 8 + g;
                    float4 bv = *(const float4*)&Wsh[o * 128 + half * 64 + ((pibase ^ (o & 1)) << 2)];
                    uint32_t b0 = __float_as_uint(bv.x), b1 = __float_as_uint(bv.y);
                    uint32_t b2 = __float_as_uint(bv.z), b3 = __float_as_uint(bv.w);
                    mma_tf32(acc[0][n], aH0m0, b0, b1);
                    mma_tf32(acc[0][n], aH1m0, b2, b3);
                    mma_tf32(acc[1][n], aH0m1, b0, b1);
                    mma_tf32(acc[1][n], aH1m1, b2, b3);
                }
            }
        }

        int mode = g_maskmode;
        #pragma unroll
        for (int m = 0; m < 2; m++) {
            int p_lo = pixBase + m * 16 + g;
            int p_hi = p_lo + 8;
            size_t gplo = (size_t)b * NPIX + p0 + p_lo;
            size_t gphi = (size_t)b * NPIX + p0 + p_hi;
            size_t milo = (size_t)s * 32768 + gplo;
            size_t mihi = (size_t)s * 32768 + gphi;
            float mvlo, mvhi;
            if (mode) {
                mvlo = ((const unsigned char*)mask)[milo] ? 1.f : 0.f;
                mvhi = ((const unsigned char*)mask)[mihi] ? 1.f : 0.f;
            } else {
                mvlo = ((const unsigned int*)mask)[milo] ? 1.f : 0.f;
                mvhi = ((const unsigned int*)mask)[mihi] ? 1.f : 0.f;
            }
            #pragma unroll
            for (int n = 0; n < 2; n++) {
                int col = oBase + n * 8 + 2 * t4;
                float2 x0 = *(const float2*)&xin[gplo * CCH + col];
                float2 x1 = *(const float2*)&xin[gphi * CCH + col];
                float2 o0 = make_float2(x0.x + acc[m][n][0] * mvlo, x0.y + acc[m][n][1] * mvlo);
                float2 o1 = make_float2(x1.x + acc[m][n][2] * mvhi, x1.y + acc[m][n][3] * mvhi);
                *(float2*)&xout[gplo * CCH + col] = o0;
                *(float2*)&xout[gphi * CCH + col] = o1;
                *(float2*)&xsh[p_lo * 64 + col] = o0;
                *(float2*)&xsh[p_hi * 64 + col] = o1;
            }
        }
    }
    __syncthreads();

    float* ysh2 = pool;
    float* WshQ = pool + 64 * 64;

    #pragma unroll
    for (int k = 0; k < 8; k++) {
        int pix = warp * 8 + k;
        float v0 = xsh[pix * 64 + lane], v1 = xsh[pix * 64 + lane + 32];
        float ss = v0 + v1, sq = v0 * v0 + v1 * v1;
        #pragma unroll
        for (int o = 16; o > 0; o >>= 1) {
            ss += __shfl_xor_sync(0xffffffffu, ss, o);
            sq += __shfl_xor_sync(0xffffffffu, sq, o);
        }
        float mu2 = ss * (1.f / 64.f);
        float rsg = rsqrtf(sq * (1.f / 64.f) - mu2 * mu2 + 1e-5f);
        float y0 = (v0 - mu2) * rsg * lw[lane] + lb[lane];
        float y1 = (v1 - mu2) * rsg * lw[lane + 32] + lb[lane + 32];
        ysh2[pix * 64 + swz_pos(lane, pix & 1)] = __uint_as_float(f2tf32(y0));
        ysh2[pix * 64 + swz_pos(lane + 32, pix & 1)] = __uint_as_float(f2tf32(y1));
    }
    {
        const float4* wsrc = (const float4*)g_QKVswz;
        float4* wdst = (float4*)WshQ;
        #pragma unroll
        for (int i = 0; i < 12; i++) wdst[i * 256 + tid] = wsrc[i * 256 + tid];
    }
    __syncthreads();

    {
        int pixBase = (warp & 1) * 32;
        int oBase = (warp >> 1) * 48;

        float acc[2][6][4];
        #pragma unroll
        for (int m = 0; m < 2; m++)
            #pragma unroll
            for (int n = 0; n < 6; n++)
                #pragma unroll
                for (int j = 0; j < 4; j++) acc[m][n][j] = 0.f;

        #pragma unroll
        for (int j = 0; j < 4; j++) {
            int pibase = t4 * 4 + ((j + t4) & 3);
            float4 av[4];
            #pragma unroll
            for (int r = 0; r < 4; r++) {
                int pr = pixBase + r * 8 + g;
                av[r] = *(const float4*)&ysh2[pr * 64 + ((pibase ^ (pr & 1)) << 2)];
            }
            uint32_t aH0m0[4] = {__float_as_uint(av[0].x), __float_as_uint(av[1].x),
                                 __float_as_uint(av[0].y), __float_as_uint(av[1].y)};
            uint32_t aH1m0[4] = {__float_as_uint(av[0].z), __float_as_uint(av[1].z),
                                 __float_as_uint(av[0].w), __float_as_uint(av[1].w)};
            uint32_t aH0m1[4] = {__float_as_uint(av[2].x), __float_as_uint(av[3].x),
                                 __float_as_uint(av[2].y), __float_as_uint(av[3].y)};
            uint32_t aH1m1[4] = {__float_as_uint(av[2].z), __float_as_uint(av[3].z),
                                 __float_as_uint(av[2].w), __float_as_uint(av[3].w)};
            #pragma unroll
            for (int n = 0; n < 6; n++) {
                int o = oBase + n * 8 + g;
                float4 bv = *(const float4*)&WshQ[o * 64 + ((pibase ^ (o & 1)) << 2)];
                uint32_t b0 = __float_as_uint(bv.x), b1 = __float_as_uint(bv.y);
                uint32_t b2 = __float_as_uint(bv.z), b3 = __float_as_uint(bv.w);
                mma_tf32(acc[0][n], aH0m0, b0, b1);
                mma_tf32(acc[0][n], aH1m0, b2, b3);
                mma_tf32(acc[1][n], aH0m1, b0, b1);
                mma_tf32(acc[1][n], aH1m1, b2, b3);
            }
        }

        #pragma unroll
        for (int m = 0; m < 2; m++) {
            int p_lo = pixBase + m * 16 + g;
            int p_hi = p_lo + 8;
            size_t gplo = (size_t)b * NPIX + p0 + p_lo;
            size_t gphi = (size_t)b * NPIX + p0 + p_hi;
            #pragma unroll
            for (int n = 0; n < 6; n++) {
                int col = oBase + n * 8 + 2 * t4;
                int region = col >> 6;
                int c = col & 63;
                float* dst = (region == 0) ? g_q : (region == 1) ? g_k : g_v;
                *(float2*)&dst[gplo * CCH + c] = make_float2(acc[m][n][0], acc[m][n][1]);
                *(float2*)&dst[gphi * CCH + c] = make_float2(acc[m][n][2], acc[m][n][3]);
            }
        }
    }
}

// ---------------- fused attn + ff, 32px/block, repacked smem: 48.1 KB -> 4 blocks/SM ----------
// layout (floats): ksh[0..3904) vsh[3904..7808) | wshp=sm[0..4224) hshp=sm[4224..6336)
//                  oshp/yshp[7808..9920) tsh[9920..12032)
#define AF_SMEM_BYTES (12032 * 4)

__global__ void __launch_bounds__(128, 4) k_attn_ff(const float* __restrict__ xn,
                                                    const float* __restrict__ xprev,
                                                    const float* __restrict__ outb,
                                                    const float* __restrict__ lw2,
                                                    const float* __restrict__ lb2,
                                                    const float* __restrict__ b1,
                                                    const float* __restrict__ b2,
                                                    float* __restrict__ xout) {
    extern __shared__ float sm[];
    float* ksh = sm;                  // [64ch][61pos]   (dead after attention)
    float* vsh = sm + 3904;           //                  (dead after attention)
    float* wshp = sm;                 // [64][66] weight overlay
    float* hshp = sm + 4224;          // [32][66] GELU out (in dead kv space)
    float* oshp = sm + 7808;          // [32][66]; aliased as yshp after phase 3
    float* tsh = sm + 9920;           // [32][66] fp32
    int tid = threadIdx.x;
    int b = blockIdx.x >> 7;
    int tile = blockIdx.x & 127;
    int tx0 = (tile & 7) << 3;
    int ty0 = (tile >> 3) << 2;
    int warp = tid >> 5, lane = tid & 31;
    int g = lane >> 2, t4 = lane & 3;
    int mw = warp & 1, nw = warp >> 1;

    #pragma unroll
    for (int i = 0; i < 30; i++) {
        int lin = tid + i * 128;
        int pos = lin >> 6, ch = lin & 63;
        int hy = pos / 10, hx = pos - hy * 10;
        int gy = ty0 + hy - 1, gx = tx0 + hx - 1;
        float kv = 0.f, vv = 0.f;
        if ((unsigned)gy < 64u && (unsigned)gx < 64u) {
            size_t a = ((size_t)b * NPIX + gy * 64 + gx) * CCH + ch;
            kv = g_k[a]; vv = g_v[a];
        }
        ksh[ch * 61 + pos] = kv;
        vsh[ch * 61 + pos] = vv;
    }
    __syncthreads();

    {
        int head = warp, lp = lane;
        int py = lp >> 3, px = lp & 7;
        int gy = ty0 + py, gx = tx0 + px;
        size_t qbase = ((size_t)b * NPIX + gy * 64 + gx) * CCH + head * 16;
        float q[16];
        #pragma unroll
        for (int i = 0; i < 4; i++) {
            float4 t4v = *(const float4*)&g_q[qbase + i * 4];
            q[i * 4] = t4v.x; q[i * 4 + 1] = t4v.y; q[i * 4 + 2] = t4v.z; q[i * 4 + 3] = t4v.w;
        }
        float lg[9];
        #pragma unroll
        for (int t = 0; t < 9; t++) {
            int pos = (py + t / 3) * 10 + px + t % 3;
            float d = 0.f;
            #pragma unroll
            for (int i = 0; i < 16; i++) d = fmaf(q[i], ksh[(head * 16 + i) * 61 + pos], d);
            lg[t] = d * ATT_SCALE;
        }
        float m = lg[0];
        #pragma unroll
        for (int t = 1; t < 9; t++) m = fmaxf(m, lg[t]);
        float e[9], ssum = 0.f;
        #pragma unroll
        for (int t = 0; t < 9; t++) { e[t] = __expf(lg[t] - m); ssum += e[t]; }
        float inv = 1.f / ssum;
        float o[16] = {};
        #pragma unroll
        for (int t = 0; t < 9; t++) {
            int pos = (py + t / 3) * 10 + px + t % 3;
            float a = e[t] * inv;
            #pragma unroll
            for (int i = 0; i < 16; i++) o[i] = fmaf(a, vsh[(head * 16 + i) * 61 + pos], o[i]);
        }
        #pragma unroll
        for (int i = 0; i < 16; i++)
            oshp[lp * 66 + pairpos(head * 16 + i)] = __uint_as_float(f2tf32(o[i]));
    }
    __syncthreads();

    // stage out-proj weights (kv region dead)
    {
        const float4* wsrc = (const float4*)g_OUTp;
        float4* wdst = (float4*)wshp;
        #pragma unroll
        for (int i = 0; i < 9; i++) {
            int idx = i * 128 + tid;
            if (idx < 1056) wdst[idx] = wsrc[idx];
        }
    }
    __syncthreads();

    // out-proj + bias + residual -> tsh
    {
        float acc[4][4] = {{0}};
        gemm_66(oshp, wshp, mw * 16, nw, g, t4, acc);
        int r0 = mw * 16 + g, r1 = r0 + 8;
        int gp0 = (ty0 + (r0 >> 3)) * 64 + tx0 + (r0 & 7);
        int gp1 = (ty0 + (r1 >> 3)) * 64 + tx0 + (r1 & 7);
        size_t b0a = ((size_t)b * NPIX + gp0) * CCH;
        size_t b1a = ((size_t)b * NPIX + gp1) * CCH;
        #pragma unroll
        for (int n = 0; n < 4; n++) {
            int col = nw * 32 + n * 8 + 2 * t4;
            tsh[r0 * 66 + col]     = acc[n][0] + outb[col]     + xn[b0a + col];
            tsh[r0 * 66 + col + 1] = acc[n][1] + outb[col + 1] + xn[b0a + col + 1];
            tsh[r1 * 66 + col]     = acc[n][2] + outb[col]     + xn[b1a + col];
            tsh[r1 * 66 + col + 1] = acc[n][3] + outb[col + 1] + xn[b1a + col + 1];
        }
    }
    __syncthreads();

    // LN2 -> yshp (aliases oshp; oshp reads finished in phase 3)
    float* yshp = oshp;
    #pragma unroll
    for (int k = 0; k < 8; k++) {
        int pix = warp * 8 + k;
        float v0 = tsh[pix * 66 + lane], v1 = tsh[pix * 66 + lane + 32];
        float ss = v0 + v1, sq = v0 * v0 + v1 * v1;
        #pragma unroll
        for (int o = 16; o > 0; o >>= 1) {
            ss += __shfl_xor_sync(0xffffffffu, ss, o);
            sq += __shfl_xor_sync(0xffffffffu, sq, o);
        }
        float mu = ss * (1.f / 64.f);
        float rsg = rsqrtf(sq * (1.f / 64.f) - mu * mu + 1e-5f);
        float y0 = (v0 - mu) * rsg * lw2[lane] + lb2[lane];
        float y1 = (v1 - mu) * rsg * lw2[lane + 32] + lb2[lane + 32];
        yshp[pix * 66 + pairpos(lane)] = __uint_as_float(f2tf32(y0));
        yshp[pix * 66 + pairpos(lane + 32)] = __uint_as_float(f2tf32(y1));
    }
    {
        const float4* wsrc = (const float4*)g_FF1p;
        float4* wdst = (float4*)wshp;
        #pragma unroll
        for (int i = 0; i < 9; i++) {
            int idx = i * 128 + tid;
            if (idx < 1056) wdst[idx] = wsrc[idx];
        }
    }
    __syncthreads();

    // ff1 + bias + GELU -> hshp
    {
        float acc[4][4] = {{0}};
        gemm_66(yshp, wshp, mw * 16, nw, g, t4, acc);
        int r0 = mw * 16 + g, r1 = r0 + 8;
        #pragma unroll
        for (int n = 0; n < 4; n++) {
            int col = nw * 32 + n * 8 + 2 * t4;
            float bb0 = b1[col], bb1 = b1[col + 1];
            float h0 = acc[n][0] + bb0, h1 = acc[n][1] + bb1;
            float h2 = acc[n][2] + bb0, h3 = acc[n][3] + bb1;
            h0 = 0.5f * h0 * (1.f + erff(h0 * 0.70710678118654752f));
            h1 = 0.5f * h1 * (1.f + erff(h1 * 0.70710678118654752f));
            h2 = 0.5f * h2 * (1.f + erff(h2 * 0.70710678118654752f));
            h3 = 0.5f * h3 * (1.f + erff(h3 * 0.70710678118654752f));
            hshp[r0 * 66 + pairpos(col)]     = __uint_as_float(f2tf32(h0));
            hshp[r0 * 66 + pairpos(col + 1)] = __uint_as_float(f2tf32(h1));
            hshp[r1 * 66 + pairpos(col)]     = __uint_as_float(f2tf32(h2));
            hshp[r1 * 66 + pairpos(col + 1)] = __uint_as_float(f2tf32(h3));
        }
    }
    __syncthreads();

    // stage ff2 weights
    {
        const float4* wsrc = (const float4*)g_FF2p;
        float4* wdst = (float4*)wshp;
        #pragma unroll
        for (int i = 0; i < 9; i++) {
            int idx = i * 128 + tid;
            if (idx < 1056) wdst[idx] = wsrc[idx];
        }
    }
    __syncthreads();

    // ff2 + bias + residual + ch0 restore -> global
    {
        float acc[4][4] = {{0}};
        gemm_66(hshp, wshp, mw * 16, nw, g, t4, acc);
        int r0 = mw * 16 + g, r1 = r0 + 8;
        int gp0 = (ty0 + (r0 >> 3)) * 64 + tx0 + (r0 & 7);
        int gp1 = (ty0 + (r1 >> 3)) * 64 + tx0 + (r1 & 7);
        size_t b0a = ((size_t)b * NPIX + gp0) * CCH;
        size_t b1a = ((size_t)b * NPIX + gp1) * CCH;
        #pragma unroll
        for (int n = 0; n < 4; n++) {
            int col = nw * 32 + n * 8 + 2 * t4;
            float v00 = acc[n][0] + b2[col]     + tsh[r0 * 66 + col];
            float v01 = acc[n][1] + b2[col + 1] + tsh[r0 * 66 + col + 1];
            float v10 = acc[n][2] + b2[col]     + tsh[r1 * 66 + col];
            float v11 = acc[n][3] + b2[col + 1] + tsh[r1 * 66 + col + 1];
            if (col == 0) { v00 = xprev[b0a]; v10 = xprev[b1a]; }
            xout[b0a + col]     = v00;
            xout[b0a + col + 1] = v01;
            xout[b1a + col]     = v10;
            xout[b1a + col + 1] = v11;
        }
    }
}

extern "C" void kernel_launch(void* const* d_in, const int* in_sizes, int n_in,
                              void* d_out, int out_size) {
    const float* x = (const float*)d_in[0];
    const void* masks = d_in[1];
    const float* p0_w = (const float*)d_in[2];
    const float* p0_b = (const float*)d_in[3];
    const float* p1_w = (const float*)d_in[4];
    const float* p1_b = (const float*)d_in[5];
    const float* fc0_w = (const float*)d_in[6];
    const float* fc0_b = (const float*)d_in[7];
    const float* fc1_w = (const float*)d_in[8];
    const float* n0w = (const float*)d_in[9];
    const float* n0b = (const float*)d_in[10];
    const float* ln1w = (const float*)d_in[11];
    const float* ln1b = (const float*)d_in[12];
    const float* qkvw = (const float*)d_in[13];
    const float* outw = (const float*)d_in[14];
    const float* outb = (const float*)d_in[15];
    const float* ln2w = (const float*)d_in[16];
    const float* ln2b = (const float*)d_in[17];
    const float* ff1w = (const float*)d_in[18];
    const float* ff1b = (const float*)d_in[19];
    const float* ff2w = (const float*)d_in[20];
    const float* ff2b = (const float*)d_in[21];
    float* out = (float*)d_out;

    cudaFuncSetAttribute(k_conv_mma, cudaFuncAttributeMaxDynamicSharedMemorySize, CONV_SMEM_BYTES);
    cudaFuncSetAttribute(k_fc1qkv, cudaFuncAttributeMaxDynamicSharedMemorySize, FQ_SMEM_BYTES);
    cudaFuncSetAttribute(k_attn_ff, cudaFuncAttributeMaxDynamicSharedMemorySize, AF_SMEM_BYTES);

    k_fold<<<288, 256>>>(fc0_w, fc0_b, p0_w, p0_b, p1_w, p1_b);
    k_prepw<<<48, 256>>>(qkvw, fc1_w, outw, ff1w, ff2w);
    k_maskdetect<<<1, 1024>>>((const unsigned char*)masks, 6 * BATCH * NPIX);

    void* sym = nullptr;
    cudaGetSymbolAddress(&sym, g_xbuf);
    float* buf0 = (float*)sym;
    float* buf1 = buf0 + BATCH * NPIX * CCH;

    const float* cur = x;
    for (int s = 0; s < 6; s++) {
        float* stage = (s & 1) ? buf1 : buf0;
        float* nxt = (s == 5) ? out : stage;
        k_conv_mma<<<256, 256, CONV_SMEM_BYTES>>>(cur);
        k_fc1qkv<<<512, 256, FQ_SMEM_BYTES>>>(cur, n0w, n0b, masks, s, stage, ln1w, ln1b);
        k_attn_ff<<<1024, 128, AF_SMEM_BYTES>>>(stage, cur, outb, ln2w, ln2b,
                                                ff1b, ff2b, nxt);
        cur = nxt;
    }
}

// round 15
// speedup vs baseline: 1.5641x; 1.0683x over previous
#include <cuda_runtime.h>
#include <math.h>
#include <stdint.h>

#define BATCH 8
#define NPIX 4096
#define CCH 64
#define HID 128
#define ATT_SCALE 0.25f

static __device__ __align__(16) float g_Wswz[9 * 128 * 64];  // pre-swizzled tf32 conv weights
static __device__ __align__(16) float g_QKVswz[192 * 64];
static __device__ __align__(16) float g_FC1swz[64 * 128];
static __device__ __align__(16) float g_OUTp[64 * 66];
static __device__ __align__(16) float g_FF1p[64 * 66];
static __device__ __align__(16) float g_FF2p[64 * 66];
static __device__ float g_beff[HID];
static __device__ float g_xbuf[2][BATCH * NPIX * CCH];
static __device__ float g_hd[BATCH * NPIX * HID];
static __device__ float g_part[256 * 2];
static __device__ float g_q[BATCH * NPIX * CCH];
static __device__ float g_k[BATCH * NPIX * CCH];
static __device__ float g_v[BATCH * NPIX * CCH];
static __device__ int g_maskmode;

__device__ __forceinline__ uint32_t f2tf32(float f) {
    uint32_t u;
    asm("cvt.rna.tf32.f32 %0, %1;" : "=r"(u) : "f"(f));
    return u;
}

__device__ __forceinline__ int swz_pos(int c, int par) {
    int t4 = c & 3, idx = c >> 2;
    int pi = (t4 * 4 + (((idx >> 2) + t4) & 3)) ^ par;
    return pi * 4 + (idx & 3);
}

__device__ __forceinline__ int pairpos(int k) {
    return (k & 56) + ((k & 3) << 1) + ((k >> 2) & 1);
}

__global__ void k_maskdetect(const unsigned char* m, int nbytes) {
    __shared__ int hasBig, hasMis;
    if (threadIdx.x == 0) { hasBig = 0; hasMis = 0; }
    __syncthreads();
    for (int i = threadIdx.x; i < nbytes; i += blockDim.x) {
        unsigned char v = m[i];
        if (v > 1) hasBig = 1;
        else if (v && (i & 3)) hasMis = 1;
    }
    __syncthreads();
    if (threadIdx.x == 0) g_maskmode = (!hasBig && hasMis) ? 1 : 0;
}

__global__ void k_fold(const float* __restrict__ fc0_w, const float* __restrict__ fc0_b,
                       const float* __restrict__ p0_w, const float* __restrict__ p0_b,
                       const float* __restrict__ p1_w, const float* __restrict__ p1_b) {
    int t = blockIdx.x * 256 + threadIdx.x;
    if (t >= HID * 576) return;
    int o = t / 576, k = t - o * 576;
    int tap = k >> 6, c = k & 63;
    const float* f1 = fc0_w + o * 192 + 64;
    const float* f2 = fc0_w + o * 192 + 128;
    float acc = 0.f;
    for (int m = 0; m < 64; m++) {
        acc = fmaf(f1[m], p0_w[(m * 64 + c) * 9 + tap], acc);
        acc = fmaf(f2[m], p1_w[(m * 64 + c) * 9 + tap], acc);
    }
    if (tap == 4) acc += fc0_w[o * 192 + c];
    g_Wswz[(tap * 128 + o) * 64 + swz_pos(c, o & 1)] = __uint_as_float(f2tf32(acc));
    if (k == 0) {
        float b = fc0_b[o];
        for (int m = 0; m < 64; m++) {
            b = fmaf(f1[m], p0_b[m], b);
            b = fmaf(f2[m], p1_b[m], b);
        }
        g_beff[o] = b;
    }
}

__global__ void k_prepw(const float* __restrict__ qkvw, const float* __restrict__ fc1w,
                        const float* __restrict__ outw, const float* __restrict__ ff1w,
                        const float* __restrict__ ff2w) {
    int t = blockIdx.x * 256 + threadIdx.x;
    if (t < 192 * 64) {
        int o = t >> 6, k = t & 63;
        g_QKVswz[o * 64 + swz_pos(k, o & 1)] = __uint_as_float(f2tf32(qkvw[t]));
    }
    if (t < 64 * 128) {
        int o = t >> 7, k = t & 127;
        int half = k >> 6, kk = k & 63;
        g_FC1swz[o * 128 + half * 64 + swz_pos(kk, o & 1)] = __uint_as_float(f2tf32(fc1w[t]));
    }
    if (t < 64 * 64) {
        int c = t >> 6, k = t & 63;
        int p = c * 66 + pairpos(k);
        g_OUTp[p] = __uint_as_float(f2tf32(outw[t]));
        g_FF1p[p] = __uint_as_float(f2tf32(ff1w[t]));
        g_FF2p[p] = __uint_as_float(f2tf32(ff2w[t]));
    }
    if (t < 128) {
        int c = t >> 1, pos = 64 + (t & 1);
        g_OUTp[c * 66 + pos] = 0.f;
        g_FF1p[c * 66 + pos] = 0.f;
        g_FF2p[c * 66 + pos] = 0.f;
    }
}

__device__ __forceinline__ int refl(int v) { return v < 0 ? -v : (v > 63 ? 126 - v : v); }

__device__ __forceinline__ void mma_tf32(float* c, const uint32_t* a, uint32_t b0, uint32_t b1) {
    asm volatile(
        "mma.sync.aligned.m16n8k8.row.col.f32.tf32.tf32.f32 "
        "{%0,%1,%2,%3}, {%4,%5,%6,%7}, {%8,%9}, {%0,%1,%2,%3};"
        : "+f"(c[0]), "+f"(c[1]), "+f"(c[2]), "+f"(c[3])
        : "r"(a[0]), "r"(a[1]), "r"(a[2]), "r"(a[3]), "r"(b0), "r"(b1));
}

// 16px x 32out x K64 per warp on pair-interleaved stride-66 operands
__device__ __forceinline__ void gemm_66(const float* __restrict__ Ap,
                                        const float* __restrict__ Wp,
                                        int rbase, int nw, int g, int t4,
                                        float acc[4][4]) {
    #pragma unroll
    for (int k0 = 0; k0 < 8; k0++) {
        int kb = k0 * 8 + 2 * t4;
        float2 a0 = *(const float2*)&Ap[(rbase + g) * 66 + kb];
        float2 a1 = *(const float2*)&Ap[(rbase + g + 8) * 66 + kb];
        uint32_t a[4] = {__float_as_uint(a0.x), __float_as_uint(a1.x),
                         __float_as_uint(a0.y), __float_as_uint(a1.y)};
        #pragma unroll
        for (int n = 0; n < 4; n++) {
            float2 b = *(const float2*)&Wp[(nw * 32 + n * 8 + g) * 66 + kb];
            mma_tf32(acc[n], a, __float_as_uint(b.x), __float_as_uint(b.y));
        }
    }
}

// ---------- conv: 128px x 128out per block; B operands via LDG from L2 (no per-tap staging) ----------
#define XH_FLOATS (264 * 64)
#define CONV_SMEM_BYTES (XH_FLOATS * 4)

__global__ void __launch_bounds__(256, 2) k_conv_mma(const float* __restrict__ xin) {
    extern __shared__ float sm[];
    float* Xh = sm;
    int tid = threadIdx.x;
    int batch = blockIdx.x >> 5;
    int y0 = (blockIdx.x & 31) << 1;
    const float* xb = xin + (size_t)batch * NPIX * CCH;

    #pragma unroll 2
    for (int i = 0; i < 66; i++) {
        int lin = i * 256 + tid;
        int ch = lin & 63;
        int hp = lin >> 6;
        int hr = hp / 66, hc = hp - hr * 66;
        int gy = refl(y0 + hr - 1), gx = refl(hc - 1);
        float v = xb[(gy * 64 + gx) * CCH + ch];
        Xh[hp * 64 + swz_pos(ch, hp & 1)] = __uint_as_float(f2tf32(v));
    }

    int warp = tid >> 5, lane = tid & 31;
    int g = lane >> 2, t4 = lane & 3;
    int pixBase = (warp >> 1) * 32;
    int nBase = (warp & 1) * 64;
    int gpar = g & 1;               // == o&1 for all our o

    // per-n weight row base (in floats), hoisted out of all loops
    int wrow[8];
    #pragma unroll
    for (int n = 0; n < 8; n++) wrow[n] = (nBase + n * 8 + g) * 64;

    float acc[2][8][4];
    #pragma unroll
    for (int m = 0; m < 2; m++)
        #pragma unroll
        for (int n = 0; n < 8; n++)
            #pragma unroll
            for (int j2 = 0; j2 < 4; j2++) acc[m][n][j2] = 0.f;

    __syncthreads();   // single barrier: halo ready

    for (int tap = 0; tap < 9; tap++) {
        int dy = tap / 3, dx = tap - dy * 3;
        const float* Wt = g_Wswz + tap * (128 * 64);
        #pragma unroll
        for (int j = 0; j < 4; j++) {
            int pibase = t4 * 4 + ((j + t4) & 3);
            int chunk = (pibase ^ gpar) << 2;     // weight chunk offset (floats)
            float4 av[4];
            #pragma unroll
            for (int r = 0; r < 4; r++) {
                int pr = pixBase + r * 8 + g;
                int hb = ((pr >> 6) + dy) * 66 + (pr & 63) + dx;
                av[r] = *(const float4*)&Xh[hb * 64 + ((pibase ^ (hb & 1)) << 2)];
            }
            uint32_t aH0m0[4] = {__float_as_uint(av[0].x), __float_as_uint(av[1].x),
                                 __float_as_uint(av[0].y), __float_as_uint(av[1].y)};
            uint32_t aH1m0[4] = {__float_as_uint(av[0].z), __float_as_uint(av[1].z),
                                 __float_as_uint(av[0].w), __float_as_uint(av[1].w)};
            uint32_t aH0m1[4] = {__float_as_uint(av[2].x), __float_as_uint(av[3].x),
                                 __float_as_uint(av[2].y), __float_as_uint(av[3].y)};
            uint32_t aH1m1[4] = {__float_as_uint(av[2].z), __float_as_uint(av[3].z),
                                 __float_as_uint(av[2].w), __float_as_uint(av[3].w)};
            // prefetch all 8 B fragments in two batches of 4 for MLP
            float4 bv0[4], bv1[4];
            #pragma unroll
            for (int n = 0; n < 4; n++)
                bv0[n] = __ldg((const float4*)&Wt[wrow[n] + chunk]);
            #pragma unroll
            for (int n = 0; n < 4; n++)
                bv1[n] = __ldg((const float4*)&Wt[wrow[4 + n] + chunk]);
            #pragma unroll
            for (int n = 0; n < 4; n++) {
                uint32_t b0 = __float_as_uint(bv0[n].x), b1 = __float_as_uint(bv0[n].y);
                uint32_t b2 = __float_as_uint(bv0[n].z), b3 = __float_as_uint(bv0[n].w);
                mma_tf32(acc[0][n], aH0m0, b0, b1);
                mma_tf32(acc[0][n], aH1m0, b2, b3);
                mma_tf32(acc[1][n], aH0m1, b0, b1);
                mma_tf32(acc[1][n], aH1m1, b2, b3);
            }
            #pragma unroll
            for (int n = 0; n < 4; n++) {
                uint32_t b0 = __float_as_uint(bv1[n].x), b1 = __float_as_uint(bv1[n].y);
                uint32_t b2 = __float_as_uint(bv1[n].z), b3 = __float_as_uint(bv1[n].w);
                mma_tf32(acc[0][4 + n], aH0m0, b0, b1);
                mma_tf32(acc[0][4 + n], aH1m0, b2, b3);
                mma_tf32(acc[1][4 + n], aH0m1, b0, b1);
                mma_tf32(acc[1][4 + n], aH1m1, b2, b3);
            }
        }
    }
    __syncthreads();   // all Xh reads done; epilogue may reuse sm

    float s = 0.f, sq = 0.f;
    #pragma unroll
    for (int m = 0; m < 2; m++) {
        int p_lo = pixBase + m * 16 + g;
        int p_hi = p_lo + 8;
        size_t row_lo = ((size_t)batch * NPIX + y0 * 64 + p_lo) * HID;
        size_t row_hi = ((size_t)batch * NPIX + y0 * 64 + p_hi) * HID;
        #pragma unroll
        for (int n = 0; n < 8; n++) {
            int col = nBase + n * 8 + 2 * t4;
            float bo0 = g_beff[col], bo1 = g_beff[col + 1];
            float r0 = fmaxf(acc[m][n][0] + bo0, 0.f);
            float r1 = fmaxf(acc[m][n][1] + bo1, 0.f);
            float r2 = fmaxf(acc[m][n][2] + bo0, 0.f);
            float r3 = fmaxf(acc[m][n][3] + bo1, 0.f);
            *(float2*)&g_hd[row_lo + col] = make_float2(r0, r1);
            *(float2*)&g_hd[row_hi + col] = make_float2(r2, r3);
            s += r0 + r1 + r2 + r3;
            sq += r0 * r0 + r1 * r1 + r2 * r2 + r3 * r3;
        }
    }
    float* red = sm;
    red[tid] = s; red[256 + tid] = sq;
    __syncthreads();
    for (int st = 128; st > 0; st >>= 1) {
        if (tid < st) { red[tid] += red[tid + st]; red[256 + tid] += red[256 + tid + st]; }
        __syncthreads();
    }
    if (tid == 0) { g_part[blockIdx.x * 2] = red[0]; g_part[blockIdx.x * 2 + 1] = red[256]; }
}

// ---------------- fused fc1 + qkv: 64 px per block (round-13 proven) ----------------
#define FQ_SMEM_BYTES ((16384 + 4096) * 4)

__global__ void __launch_bounds__(256, 2) k_fc1qkv(const float* __restrict__ xin,
                                                   const float* __restrict__ nw,
                                                   const float* __restrict__ nb,
                                                   const void* __restrict__ mask, int s,
                                                   float* __restrict__ xout,
                                                   const float* __restrict__ lw,
                                                   const float* __restrict__ lb) {
    extern __shared__ float sm[];
    float* pool = sm;
    float* xsh = sm + 16384;
    __shared__ float s_mu, s_rs;
    int tid = threadIdx.x;
    int b = blockIdx.x >> 6;
    int p0 = (blockIdx.x & 63) << 6;
    int warp = tid >> 5, lane = tid & 31;
    int g = lane >> 2, t4 = lane & 3;

    float* ysh = pool;
    float* Wsh = pool + 64 * 128;

    if (tid < 32) {
        float ss = g_part[(b * 32 + tid) * 2];
        float sq = g_part[(b * 32 + tid) * 2 + 1];
        #pragma unroll
        for (int o = 16; o > 0; o >>= 1) {
            ss += __shfl_xor_sync(0xffffffffu, ss, o);
            sq += __shfl_xor_sync(0xffffffffu, sq, o);
        }
        if (tid == 0) {
            const float inv = 1.f / 524288.f;
            float mu = ss * inv;
            s_mu = mu;
            s_rs = rsqrtf(sq * inv - mu * mu + 1e-5f);
        }
    }
    {
        const float4* wsrc = (const float4*)g_FC1swz;
        float4* wdst = (float4*)Wsh;
        #pragma unroll
        for (int i = 0; i < 8; i++) wdst[i * 256 + tid] = wsrc[i * 256 + tid];
    }
    __syncthreads();
    float mu = s_mu, rs = s_rs;

    #pragma unroll
    for (int i = 0; i < 32; i++) {
        int lin = i * 256 + tid;
        int pix = lin >> 7, kk = lin & 127;
        size_t gi = ((size_t)b * NPIX + p0 + pix) * HID + kk;
        int ii = (p0 + pix) * HID + kk;
        float y = (g_hd[gi] - mu) * rs * nw[ii] + nb[ii];
        int half = kk >> 6, kc = kk & 63;
        ysh[pix * 128 + half * 64 + swz_pos(kc, pix & 1)] = __uint_as_float(f2tf32(y));
    }
    __syncthreads();

    {
        int pixBase = (warp & 1) * 32;
        int oBase = (warp >> 1) * 16;

        float acc[2][2][4];
        #pragma unroll
        for (int m = 0; m < 2; m++)
            #pragma unroll
            for (int n = 0; n < 2; n++)
                #pragma unroll
                for (int j = 0; j < 4; j++) acc[m][n][j] = 0.f;

        #pragma unroll
        for (int half = 0; half < 2; half++) {
            #pragma unroll
            for (int j = 0; j < 4; j++) {
                int pibase = t4 * 4 + ((j + t4) & 3);
                float4 av[4];
                #pragma unroll
                for (int r = 0; r < 4; r++) {
                    int pr = pixBase + r * 8 + g;
                    av[r] = *(const float4*)&ysh[pr * 128 + half * 64 + ((pibase ^ (pr & 1)) << 2)];
                }
                uint32_t aH0m0[4] = {__float_as_uint(av[0].x), __float_as_uint(av[1].x),
                                     __float_as_uint(av[0].y), __float_as_uint(av[1].y)};
                uint32_t aH1m0[4] = {__float_as_uint(av[0].z), __float_as_uint(av[1].z),
                                     __float_as_uint(av[0].w), __float_as_uint(av[1].w)};
                uint32_t aH0m1[4] = {__float_as_uint(av[2].x), __float_as_uint(av[3].x),
                                     __float_as_uint(av[2].y), __float_as_uint(av[3].y)};
                uint32_t aH1m1[4] = {__float_as_uint(av[2].z), __float_as_uint(av[3].z),
                                     __float_as_uint(av[2].w), __float_as_uint(av[3].w)};
                #pragma unroll
                for (int n = 0; n < 2; n++) {
                    int o = oBase + n * 8 + g;
                    float4 bv = *(const float4*)&Wsh[o * 128 + half * 64 + ((pibase ^ (o & 1)) << 2)];
                    uint32_t b0 = __float_as_uint(bv.x), b1 = __float_as_uint(bv.y);
                    uint32_t b2 = __float_as_uint(bv.z), b3 = __float_as_uint(bv.w);
                    mma_tf32(acc[0][n], aH0m0, b0, b1);
                    mma_tf32(acc[0][n], aH1m0, b2, b3);
                    mma_tf32(acc[1][n], aH0m1, b0, b1);
                    mma_tf32(acc[1][n], aH1m1, b2, b3);
                }
            }
        }

        int mode = g_maskmode;
        #pragma unroll
        for (int m = 0; m < 2; m++) {
            int p_lo = pixBase + m * 16 + g;
            int p_hi = p_lo + 8;
            size_t gplo = (size_t)b * NPIX + p0 + p_lo;
            size_t gphi = (size_t)b * NPIX + p0 + p_hi;
            size_t milo = (size_t)s * 32768 + gplo;
            size_t mihi = (size_t)s * 32768 + gphi;
            float mvlo, mvhi;
            if (mode) {
                mvlo = ((const unsigned char*)mask)[milo] ? 1.f : 0.f;
                mvhi = ((const unsigned char*)mask)[mihi] ? 1.f : 0.f;
            } else {
                mvlo = ((const unsigned int*)mask)[milo] ? 1.f : 0.f;
                mvhi = ((const unsigned int*)mask)[mihi] ? 1.f : 0.f;
            }
            #pragma unroll
            for (int n = 0; n < 2; n++) {
                int col = oBase + n * 8 + 2 * t4;
                float2 x0 = *(const float2*)&xin[gplo * CCH + col];
                float2 x1 = *(const float2*)&xin[gphi * CCH + col];
                float2 o0 = make_float2(x0.x + acc[m][n][0] * mvlo, x0.y + acc[m][n][1] * mvlo);
                float2 o1 = make_float2(x1.x + acc[m][n][2] * mvhi, x1.y + acc[m][n][3] * mvhi);
                *(float2*)&xout[gplo * CCH + col] = o0;
                *(float2*)&xout[gphi * CCH + col] = o1;
                *(float2*)&xsh[p_lo * 64 + col] = o0;
                *(float2*)&xsh[p_hi * 64 + col] = o1;
            }
        }
    }
    __syncthreads();

    float* ysh2 = pool;
    float* WshQ = pool + 64 * 64;

    #pragma unroll
    for (int k = 0; k < 8; k++) {
        int pix = warp * 8 + k;
        float v0 = xsh[pix * 64 + lane], v1 = xsh[pix * 64 + lane + 32];
        float ss = v0 + v1, sq = v0 * v0 + v1 * v1;
        #pragma unroll
        for (int o = 16; o > 0; o >>= 1) {
            ss += __shfl_xor_sync(0xffffffffu, ss, o);
            sq += __shfl_xor_sync(0xffffffffu, sq, o);
        }
        float mu2 = ss * (1.f / 64.f);
        float rsg = rsqrtf(sq * (1.f / 64.f) - mu2 * mu2 + 1e-5f);
        float y0 = (v0 - mu2) * rsg * lw[lane] + lb[lane];
        float y1 = (v1 - mu2) * rsg * lw[lane + 32] + lb[lane + 32];
        ysh2[pix * 64 + swz_pos(lane, pix & 1)] = __uint_as_float(f2tf32(y0));
        ysh2[pix * 64 + swz_pos(lane + 32, pix & 1)] = __uint_as_float(f2tf32(y1));
    }
    {
        const float4* wsrc = (const float4*)g_QKVswz;
        float4* wdst = (float4*)WshQ;
        #pragma unroll
        for (int i = 0; i < 12; i++) wdst[i * 256 + tid] = wsrc[i * 256 + tid];
    }
    __syncthreads();

    {
        int pixBase = (warp & 1) * 32;
        int oBase = (warp >> 1) * 48;

        float acc[2][6][4];
        #pragma unroll
        for (int m = 0; m < 2; m++)
            #pragma unroll
            for (int n = 0; n < 6; n++)
                #pragma unroll
                for (int j = 0; j < 4; j++) acc[m][n][j] = 0.f;

        #pragma unroll
        for (int j = 0; j < 4; j++) {
            int pibase = t4 * 4 + ((j + t4) & 3);
            float4 av[4];
            #pragma unroll
            for (int r = 0; r < 4; r++) {
                int pr = pixBase + r * 8 + g;
                av[r] = *(const float4*)&ysh2[pr * 64 + ((pibase ^ (pr & 1)) << 2)];
            }
            uint32_t aH0m0[4] = {__float_as_uint(av[0].x), __float_as_uint(av[1].x),
                                 __float_as_uint(av[0].y), __float_as_uint(av[1].y)};
            uint32_t aH1m0[4] = {__float_as_uint(av[0].z), __float_as_uint(av[1].z),
                                 __float_as_uint(av[0].w), __float_as_uint(av[1].w)};
            uint32_t aH0m1[4] = {__float_as_uint(av[2].x), __float_as_uint(av[3].x),
                                 __float_as_uint(av[2].y), __float_as_uint(av[3].y)};
            uint32_t aH1m1[4] = {__float_as_uint(av[2].z), __float_as_uint(av[3].z),
                                 __float_as_uint(av[2].w), __float_as_uint(av[3].w)};
            #pragma unroll
            for (int n = 0; n < 6; n++) {
                int o = oBase + n * 8 + g;
                float4 bv = *(const float4*)&WshQ[o * 64 + ((pibase ^ (o & 1)) << 2)];
                uint32_t b0 = __float_as_uint(bv.x), b1 = __float_as_uint(bv.y);
                uint32_t b2 = __float_as_uint(bv.z), b3 = __float_as_uint(bv.w);
                mma_tf32(acc[0][n], aH0m0, b0, b1);
                mma_tf32(acc[0][n], aH1m0, b2, b3);
                mma_tf32(acc[1][n], aH0m1, b0, b1);
                mma_tf32(acc[1][n], aH1m1, b2, b3);
            }
        }

        #pragma unroll
        for (int m = 0; m < 2; m++) {
            int p_lo = pixBase + m * 16 + g;
            int p_hi = p_lo + 8;
            size_t gplo = (size_t)b * NPIX + p0 + p_lo;
            size_t gphi = (size_t)b * NPIX + p0 + p_hi;
            #pragma unroll
            for (int n = 0; n < 6; n++) {
                int col = oBase + n * 8 + 2 * t4;
                int region = col >> 6;
                int c = col & 63;
                float* dst = (region == 0) ? g_q : (region == 1) ? g_k : g_v;
                *(float2*)&dst[gplo * CCH + c] = make_float2(acc[m][n][0], acc[m][n][1]);
                *(float2*)&dst[gphi * CCH + c] = make_float2(acc[m][n][2], acc[m][n][3]);
            }
        }
    }
}

// ---------------- fused attn + ff, 32px/block, 48.1 KB smem, 4 blocks/SM (round-13) ----------
#define AF_SMEM_BYTES (12032 * 4)

__global__ void __launch_bounds__(128, 4) k_attn_ff(const float* __restrict__ xn,
                                                    const float* __restrict__ xprev,
                                                    const float* __restrict__ outb,
                                                    const float* __restrict__ lw2,
                                                    const float* __restrict__ lb2,
                                                    const float* __restrict__ b1,
                                                    const float* __restrict__ b2,
                                                    float* __restrict__ xout) {
    extern __shared__ float sm[];
    float* ksh = sm;
    float* vsh = sm + 3904;
    float* wshp = sm;
    float* hshp = sm + 4224;
    float* oshp = sm + 7808;
    float* tsh = sm + 9920;
    int tid = threadIdx.x;
    int b = blockIdx.x >> 7;
    int tile = blockIdx.x & 127;
    int tx0 = (tile & 7) << 3;
    int ty0 = (tile >> 3) << 2;
    int warp = tid >> 5, lane = tid & 31;
    int g = lane >> 2, t4 = lane & 3;
    int mw = warp & 1, nw = warp >> 1;

    #pragma unroll
    for (int i = 0; i < 30; i++) {
        int lin = tid + i * 128;
        int pos = lin >> 6, ch = lin & 63;
        int hy = pos / 10, hx = pos - hy * 10;
        int gy = ty0 + hy - 1, gx = tx0 + hx - 1;
        float kv = 0.f, vv = 0.f;
        if ((unsigned)gy < 64u && (unsigned)gx < 64u) {
            size_t a = ((size_t)b * NPIX + gy * 64 + gx) * CCH + ch;
            kv = g_k[a]; vv = g_v[a];
        }
        ksh[ch * 61 + pos] = kv;
        vsh[ch * 61 + pos] = vv;
    }
    __syncthreads();

    {
        int head = warp, lp = lane;
        int py = lp >> 3, px = lp & 7;
        int gy = ty0 + py, gx = tx0 + px;
        size_t qbase = ((size_t)b * NPIX + gy * 64 + gx) * CCH + head * 16;
        float q[16];
        #pragma unroll
        for (int i = 0; i < 4; i++) {
            float4 t4v = *(const float4*)&g_q[qbase + i * 4];
            q[i * 4] = t4v.x; q[i * 4 + 1] = t4v.y; q[i * 4 + 2] = t4v.z; q[i * 4 + 3] = t4v.w;
        }
        float lg[9];
        #pragma unroll
        for (int t = 0; t < 9; t++) {
            int pos = (py + t / 3) * 10 + px + t % 3;
            float d = 0.f;
            #pragma unroll
            for (int i = 0; i < 16; i++) d = fmaf(q[i], ksh[(head * 16 + i) * 61 + pos], d);
            lg[t] = d * ATT_SCALE;
        }
        float m = lg[0];
        #pragma unroll
        for (int t = 1; t < 9; t++) m = fmaxf(m, lg[t]);
        float e[9], ssum = 0.f;
        #pragma unroll
        for (int t = 0; t < 9; t++) { e[t] = __expf(lg[t] - m); ssum += e[t]; }
        float inv = 1.f / ssum;
        float o[16] = {};
        #pragma unroll
        for (int t = 0; t < 9; t++) {
            int pos = (py + t / 3) * 10 + px + t % 3;
            float a = e[t] * inv;
            #pragma unroll
            for (int i = 0; i < 16; i++) o[i] = fmaf(a, vsh[(head * 16 + i) * 61 + pos], o[i]);
        }
        #pragma unroll
        for (int i = 0; i < 16; i++)
            oshp[lp * 66 + pairpos(head * 16 + i)] = __uint_as_float(f2tf32(o[i]));
    }
    __syncthreads();

    {
        const float4* wsrc = (const float4*)g_OUTp;
        float4* wdst = (float4*)wshp;
        #pragma unroll
        for (int i = 0; i < 9; i++) {
            int idx = i * 128 + tid;
            if (idx < 1056) wdst[idx] = wsrc[idx];
        }
    }
    __syncthreads();

    {
        float acc[4][4] = {{0}};
        gemm_66(oshp, wshp, mw * 16, nw, g, t4, acc);
        int r0 = mw * 16 + g, r1 = r0 + 8;
        int gp0 = (ty0 + (r0 >> 3)) * 64 + tx0 + (r0 & 7);
        int gp1 = (ty0 + (r1 >> 3)) * 64 + tx0 + (r1 & 7);
        size_t b0a = ((size_t)b * NPIX + gp0) * CCH;
        size_t b1a = ((size_t)b * NPIX + gp1) * CCH;
        #pragma unroll
        for (int n = 0; n < 4; n++) {
            int col = nw * 32 + n * 8 + 2 * t4;
            tsh[r0 * 66 + col]     = acc[n][0] + outb[col]     + xn[b0a + col];
            tsh[r0 * 66 + col + 1] = acc[n][1] + outb[col + 1] + xn[b0a + col + 1];
            tsh[r1 * 66 + col]     = acc[n][2] + outb[col]     + xn[b1a + col];
            tsh[r1 * 66 + col + 1] = acc[n][3] + outb[col + 1] + xn[b1a + col + 1];
        }
    }
    __syncthreads();

    float* yshp = oshp;
    #pragma unroll
    for (int k = 0; k < 8; k++) {
        int pix = warp * 8 + k;
        float v0 = tsh[pix * 66 + lane], v1 = tsh[pix * 66 + lane + 32];
        float ss = v0 + v1, sq = v0 * v0 + v1 * v1;
        #pragma unroll
        for (int o = 16; o > 0; o >>= 1) {
            ss += __shfl_xor_sync(0xffffffffu, ss, o);
            sq += __shfl_xor_sync(0xffffffffu, sq, o);
        }
        float mu = ss * (1.f / 64.f);
        float rsg = rsqrtf(sq * (1.f / 64.f) - mu * mu + 1e-5f);
        float y0 = (v0 - mu) * rsg * lw2[lane] + lb2[lane];
        float y1 = (v1 - mu) * rsg * lw2[lane + 32] + lb2[lane + 32];
        yshp[pix * 66 + pairpos(lane)] = __uint_as_float(f2tf32(y0));
        yshp[pix * 66 + pairpos(lane + 32)] = __uint_as_float(f2tf32(y1));
    }
    {
        const float4* wsrc = (const float4*)g_FF1p;
        float4* wdst = (float4*)wshp;
        #pragma unroll
        for (int i = 0; i < 9; i++) {
            int idx = i * 128 + tid;
            if (idx < 1056) wdst[idx] = wsrc[idx];
        }
    }
    __syncthreads();

    {
        float acc[4][4] = {{0}};
        gemm_66(yshp, wshp, mw * 16, nw, g, t4, acc);
        int r0 = mw * 16 + g, r1 = r0 + 8;
        #pragma unroll
        for (int n = 0; n < 4; n++) {
            int col = nw * 32 + n * 8 + 2 * t4;
            float bb0 = b1[col], bb1 = b1[col + 1];
            float h0 = acc[n][0] + bb0, h1 = acc[n][1] + bb1;
            float h2 = acc[n][2] + bb0, h3 = acc[n][3] + bb1;
            h0 = 0.5f * h0 * (1.f + erff(h0 * 0.70710678118654752f));
            h1 = 0.5f * h1 * (1.f + erff(h1 * 0.70710678118654752f));
            h2 = 0.5f * h2 * (1.f + erff(h2 * 0.70710678118654752f));
            h3 = 0.5f * h3 * (1.f + erff(h3 * 0.70710678118654752f));
            hshp[r0 * 66 + pairpos(col)]     = __uint_as_float(f2tf32(h0));
            hshp[r0 * 66 + pairpos(col + 1)] = __uint_as_float(f2tf32(h1));
            hshp[r1 * 66 + pairpos(col)]     = __uint_as_float(f2tf32(h2));
            hshp[r1 * 66 + pairpos(col + 1)] = __uint_as_float(f2tf32(h3));
        }
    }
    __syncthreads();

    {
        const float4* wsrc = (const float4*)g_FF2p;
        float4* wdst = (float4*)wshp;
        #pragma unroll
        for (int i = 0; i < 9; i++) {
            int idx = i * 128 + tid;
            if (idx < 1056) wdst[idx] = wsrc[idx];
        }
    }
    __syncthreads();

    {
        float acc[4][4] = {{0}};
        gemm_66(hshp, wshp, mw * 16, nw, g, t4, acc);
        int r0 = mw * 16 + g, r1 = r0 + 8;
        int gp0 = (ty0 + (r0 >> 3)) * 64 + tx0 + (r0 & 7);
        int gp1 = (ty0 + (r1 >> 3)) * 64 + tx0 + (r1 & 7);
        size_t b0a = ((size_t)b * NPIX + gp0) * CCH;
        size_t b1a = ((size_t)b * NPIX + gp1) * CCH;
        #pragma unroll
        for (int n = 0; n < 4; n++) {
            int col = nw * 32 + n * 8 + 2 * t4;
            float v00 = acc[n][0] + b2[col]     + tsh[r0 * 66 + col];
            float v01 = acc[n][1] + b2[col + 1] + tsh[r0 * 66 + col + 1];
            float v10 = acc[n][2] + b2[col]     + tsh[r1 * 66 + col];
            float v11 = acc[n][3] + b2[col + 1] + tsh[r1 * 66 + col + 1];
            if (col == 0) { v00 = xprev[b0a]; v10 = xprev[b1a]; }
            xout[b0a + col]     = v00;
            xout[b0a + col + 1] = v01;
            xout[b1a + col]     = v10;
            xout[b1a + col + 1] = v11;
        }
    }
}

extern "C" void kernel_launch(void* const* d_in, const int* in_sizes, int n_in,
                              void* d_out, int out_size) {
    const float* x = (const float*)d_in[0];
    const void* masks = d_in[1];
    const float* p0_w = (const float*)d_in[2];
    const float* p0_b = (const float*)d_in[3];
    const float* p1_w = (const float*)d_in[4];
    const float* p1_b = (const float*)d_in[5];
    const float* fc0_w = (const float*)d_in[6];
    const float* fc0_b = (const float*)d_in[7];
    const float* fc1_w = (const float*)d_in[8];
    const float* n0w = (const float*)d_in[9];
    const float* n0b = (const float*)d_in[10];
    const float* ln1w = (const float*)d_in[11];
    const float* ln1b = (const float*)d_in[12];
    const float* qkvw = (const float*)d_in[13];
    const float* outw = (const float*)d_in[14];
    const float* outb = (const float*)d_in[15];
    const float* ln2w = (const float*)d_in[16];
    const float* ln2b = (const float*)d_in[17];
    const float* ff1w = (const float*)d_in[18];
    const float* ff1b = (const float*)d_in[19];
    const float* ff2w = (const float*)d_in[20];
    const float* ff2b = (const float*)d_in[21];
    float* out = (float*)d_out;

    cudaFuncSetAttribute(k_conv_mma, cudaFuncAttributeMaxDynamicSharedMemorySize, CONV_SMEM_BYTES);
    cudaFuncSetAttribute(k_fc1qkv, cudaFuncAttributeMaxDynamicSharedMemorySize, FQ_SMEM_BYTES);
    cudaFuncSetAttribute(k_attn_ff, cudaFuncAttributeMaxDynamicSharedMemorySize, AF_SMEM_BYTES);

    k_fold<<<288, 256>>>(fc0_w, fc0_b, p0_w, p0_b, p1_w, p1_b);
    k_prepw<<<48, 256>>>(qkvw, fc1_w, outw, ff1w, ff2w);
    k_maskdetect<<<1, 1024>>>((const unsigned char*)masks, 6 * BATCH * NPIX);

    void* sym = nullptr;
    cudaGetSymbolAddress(&sym, g_xbuf);
    float* buf0 = (float*)sym;
    float* buf1 = buf0 + BATCH * NPIX * CCH;

    const float* cur = x;
    for (int s = 0; s < 6; s++) {
        float* stage = (s & 1) ? buf1 : buf0;
        float* nxt = (s == 5) ? out : stage;
        k_conv_mma<<<256, 256, CONV_SMEM_BYTES>>>(cur);
        k_fc1qkv<<<512, 256, FQ_SMEM_BYTES>>>(cur, n0w, n0b, masks, s, stage, ln1w, ln1b);
        k_attn_ff<<<1024, 128, AF_SMEM_BYTES>>>(stage, cur, outb, ln2w, ln2b,
                                                ff1b, ff2b, nxt);
        cur = nxt;
    }
}

// round 16
// speedup vs baseline: 1.6303x; 1.0423x over previous
#include <cuda_runtime.h>
#include <math.h>
#include <stdint.h>

#define BATCH 8
#define NPIX 4096
#define CCH 64
#define HID 128
#define ATT_SCALE 0.25f

static __device__ __align__(16) float g_Wswz[9 * 128 * 64];  // pre-swizzled tf32 conv weights
static __device__ __align__(16) float g_QKVswz[192 * 64];
static __device__ __align__(16) float g_FC1swz[64 * 128];
static __device__ __align__(16) float g_OUTp[64 * 66];
static __device__ __align__(16) float g_FF1p[64 * 66];
static __device__ __align__(16) float g_FF2p[64 * 66];
static __device__ float g_beff[HID];
static __device__ float g_xbuf[2][BATCH * NPIX * CCH];
static __device__ float g_hd[BATCH * NPIX * HID];
static __device__ float g_part[256 * 2];
static __device__ float g_q[BATCH * NPIX * CCH];
static __device__ float g_k[BATCH * NPIX * CCH];
static __device__ float g_v[BATCH * NPIX * CCH];
static __device__ int g_maskmode;

__device__ __forceinline__ uint32_t f2tf32(float f) {
    uint32_t u;
    asm("cvt.rna.tf32.f32 %0, %1;" : "=r"(u) : "f"(f));
    return u;
}

__device__ __forceinline__ int swz_pos(int c, int par) {
    int t4 = c & 3, idx = c >> 2;
    int pi = (t4 * 4 + (((idx >> 2) + t4) & 3)) ^ par;
    return pi * 4 + (idx & 3);
}

__device__ __forceinline__ int pairpos(int k) {
    return (k & 56) + ((k & 3) << 1) + ((k >> 2) & 1);
}

__global__ void k_maskdetect(const unsigned char* m, int nbytes) {
    __shared__ int hasBig, hasMis;
    if (threadIdx.x == 0) { hasBig = 0; hasMis = 0; }
    __syncthreads();
    for (int i = threadIdx.x; i < nbytes; i += blockDim.x) {
        unsigned char v = m[i];
        if (v > 1) hasBig = 1;
        else if (v && (i & 3)) hasMis = 1;
    }
    __syncthreads();
    if (threadIdx.x == 0) g_maskmode = (!hasBig && hasMis) ? 1 : 0;
}

__global__ void k_fold(const float* __restrict__ fc0_w, const float* __restrict__ fc0_b,
                       const float* __restrict__ p0_w, const float* __restrict__ p0_b,
                       const float* __restrict__ p1_w, const float* __restrict__ p1_b) {
    int t = blockIdx.x * 256 + threadIdx.x;
    if (t >= HID * 576) return;
    int o = t / 576, k = t - o * 576;
    int tap = k >> 6, c = k & 63;
    const float* f1 = fc0_w + o * 192 + 64;
    const float* f2 = fc0_w + o * 192 + 128;
    float acc = 0.f;
    for (int m = 0; m < 64; m++) {
        acc = fmaf(f1[m], p0_w[(m * 64 + c) * 9 + tap], acc);
        acc = fmaf(f2[m], p1_w[(m * 64 + c) * 9 + tap], acc);
    }
    if (tap == 4) acc += fc0_w[o * 192 + c];
    g_Wswz[(tap * 128 + o) * 64 + swz_pos(c, o & 1)] = __uint_as_float(f2tf32(acc));
    if (k == 0) {
        float b = fc0_b[o];
        for (int m = 0; m < 64; m++) {
            b = fmaf(f1[m], p0_b[m], b);
            b = fmaf(f2[m], p1_b[m], b);
        }
        g_beff[o] = b;
    }
}

__global__ void k_prepw(const float* __restrict__ qkvw, const float* __restrict__ fc1w,
                        const float* __restrict__ outw, const float* __restrict__ ff1w,
                        const float* __restrict__ ff2w) {
    int t = blockIdx.x * 256 + threadIdx.x;
    if (t < 192 * 64) {
        int o = t >> 6, k = t & 63;
        g_QKVswz[o * 64 + swz_pos(k, o & 1)] = __uint_as_float(f2tf32(qkvw[t]));
    }
    if (t < 64 * 128) {
        int o = t >> 7, k = t & 127;
        int half = k >> 6, kk = k & 63;
        g_FC1swz[o * 128 + half * 64 + swz_pos(kk, o & 1)] = __uint_as_float(f2tf32(fc1w[t]));
    }
    if (t < 64 * 64) {
        int c = t >> 6, k = t & 63;
        int p = c * 66 + pairpos(k);
        g_OUTp[p] = __uint_as_float(f2tf32(outw[t]));
        g_FF1p[p] = __uint_as_float(f2tf32(ff1w[t]));
        g_FF2p[p] = __uint_as_float(f2tf32(ff2w[t]));
    }
    if (t < 128) {
        int c = t >> 1, pos = 64 + (t & 1);
        g_OUTp[c * 66 + pos] = 0.f;
        g_FF1p[c * 66 + pos] = 0.f;
        g_FF2p[c * 66 + pos] = 0.f;
    }
}

__device__ __forceinline__ int refl(int v) { return v < 0 ? -v : (v > 63 ? 126 - v : v); }

__device__ __forceinline__ void mma_tf32(float* c, const uint32_t* a, uint32_t b0, uint32_t b1) {
    asm volatile(
        "mma.sync.aligned.m16n8k8.row.col.f32.tf32.tf32.f32 "
        "{%0,%1,%2,%3}, {%4,%5,%6,%7}, {%8,%9}, {%0,%1,%2,%3};"
        : "+f"(c[0]), "+f"(c[1]), "+f"(c[2]), "+f"(c[3])
        : "r"(a[0]), "r"(a[1]), "r"(a[2]), "r"(a[3]), "r"(b0), "r"(b1));
}

// 16px x 32out x K64 per warp; A from smem (stride-66 pair-interleaved), B via LDG from global
__device__ __forceinline__ void gemm_66g(const float* __restrict__ Ap,
                                         const float* __restrict__ Wg,
                                         int rbase, int nw, int g, int t4,
                                         float acc[4][4]) {
    #pragma unroll
    for (int k0 = 0; k0 < 8; k0++) {
        int kb = k0 * 8 + 2 * t4;
        float2 a0 = *(const float2*)&Ap[(rbase + g) * 66 + kb];
        float2 a1 = *(const float2*)&Ap[(rbase + g + 8) * 66 + kb];
        uint32_t a[4] = {__float_as_uint(a0.x), __float_as_uint(a1.x),
                         __float_as_uint(a0.y), __float_as_uint(a1.y)};
        #pragma unroll
        for (int n = 0; n < 4; n++) {
            float2 b = __ldg((const float2*)&Wg[(nw * 32 + n * 8 + g) * 66 + kb]);
            mma_tf32(acc[n], a, __float_as_uint(b.x), __float_as_uint(b.y));
        }
    }
}

// ---------- conv: 128px x 128out per block; B operands via LDG from L2 (round-15 proven) ----------
#define XH_FLOATS (264 * 64)
#define CONV_SMEM_BYTES (XH_FLOATS * 4)

__global__ void __launch_bounds__(256, 2) k_conv_mma(const float* __restrict__ xin) {
    extern __shared__ float sm[];
    float* Xh = sm;
    int tid = threadIdx.x;
    int batch = blockIdx.x >> 5;
    int y0 = (blockIdx.x & 31) << 1;
    const float* xb = xin + (size_t)batch * NPIX * CCH;

    #pragma unroll 2
    for (int i = 0; i < 66; i++) {
        int lin = i * 256 + tid;
        int ch = lin & 63;
        int hp = lin >> 6;
        int hr = hp / 66, hc = hp - hr * 66;
        int gy = refl(y0 + hr - 1), gx = refl(hc - 1);
        float v = xb[(gy * 64 + gx) * CCH + ch];
        Xh[hp * 64 + swz_pos(ch, hp & 1)] = __uint_as_float(f2tf32(v));
    }

    int warp = tid >> 5, lane = tid & 31;
    int g = lane >> 2, t4 = lane & 3;
    int pixBase = (warp >> 1) * 32;
    int nBase = (warp & 1) * 64;
    int gpar = g & 1;

    int wrow[8];
    #pragma unroll
    for (int n = 0; n < 8; n++) wrow[n] = (nBase + n * 8 + g) * 64;

    float acc[2][8][4];
    #pragma unroll
    for (int m = 0; m < 2; m++)
        #pragma unroll
        for (int n = 0; n < 8; n++)
            #pragma unroll
            for (int j2 = 0; j2 < 4; j2++) acc[m][n][j2] = 0.f;

    __syncthreads();

    for (int tap = 0; tap < 9; tap++) {
        int dy = tap / 3, dx = tap - dy * 3;
        const float* Wt = g_Wswz + tap * (128 * 64);
        #pragma unroll
        for (int j = 0; j < 4; j++) {
            int pibase = t4 * 4 + ((j + t4) & 3);
            int chunk = (pibase ^ gpar) << 2;
            float4 av[4];
            #pragma unroll
            for (int r = 0; r < 4; r++) {
                int pr = pixBase + r * 8 + g;
                int hb = ((pr >> 6) + dy) * 66 + (pr & 63) + dx;
                av[r] = *(const float4*)&Xh[hb * 64 + ((pibase ^ (hb & 1)) << 2)];
            }
            uint32_t aH0m0[4] = {__float_as_uint(av[0].x), __float_as_uint(av[1].x),
                                 __float_as_uint(av[0].y), __float_as_uint(av[1].y)};
            uint32_t aH1m0[4] = {__float_as_uint(av[0].z), __float_as_uint(av[1].z),
                                 __float_as_uint(av[0].w), __float_as_uint(av[1].w)};
            uint32_t aH0m1[4] = {__float_as_uint(av[2].x), __float_as_uint(av[3].x),
                                 __float_as_uint(av[2].y), __float_as_uint(av[3].y)};
            uint32_t aH1m1[4] = {__float_as_uint(av[2].z), __float_as_uint(av[3].z),
                                 __float_as_uint(av[2].w), __float_as_uint(av[3].w)};
            float4 bv0[4], bv1[4];
            #pragma unroll
            for (int n = 0; n < 4; n++)
                bv0[n] = __ldg((const float4*)&Wt[wrow[n] + chunk]);
            #pragma unroll
            for (int n = 0; n < 4; n++)
                bv1[n] = __ldg((const float4*)&Wt[wrow[4 + n] + chunk]);
            #pragma unroll
            for (int n = 0; n < 4; n++) {
                uint32_t b0 = __float_as_uint(bv0[n].x), b1 = __float_as_uint(bv0[n].y);
                uint32_t b2 = __float_as_uint(bv0[n].z), b3 = __float_as_uint(bv0[n].w);
                mma_tf32(acc[0][n], aH0m0, b0, b1);
                mma_tf32(acc[0][n], aH1m0, b2, b3);
                mma_tf32(acc[1][n], aH0m1, b0, b1);
                mma_tf32(acc[1][n], aH1m1, b2, b3);
            }
            #pragma unroll
            for (int n = 0; n < 4; n++) {
                uint32_t b0 = __float_as_uint(bv1[n].x), b1 = __float_as_uint(bv1[n].y);
                uint32_t b2 = __float_as_uint(bv1[n].z), b3 = __float_as_uint(bv1[n].w);
                mma_tf32(acc[0][4 + n], aH0m0, b0, b1);
                mma_tf32(acc[0][4 + n], aH1m0, b2, b3);
                mma_tf32(acc[1][4 + n], aH0m1, b0, b1);
                mma_tf32(acc[1][4 + n], aH1m1, b2, b3);
            }
        }
    }
    __syncthreads();

    float s = 0.f, sq = 0.f;
    #pragma unroll
    for (int m = 0; m < 2; m++) {
        int p_lo = pixBase + m * 16 + g;
        int p_hi = p_lo + 8;
        size_t row_lo = ((size_t)batch * NPIX + y0 * 64 + p_lo) * HID;
        size_t row_hi = ((size_t)batch * NPIX + y0 * 64 + p_hi) * HID;
        #pragma unroll
        for (int n = 0; n < 8; n++) {
            int col = nBase + n * 8 + 2 * t4;
            float bo0 = g_beff[col], bo1 = g_beff[col + 1];
            float r0 = fmaxf(acc[m][n][0] + bo0, 0.f);
            float r1 = fmaxf(acc[m][n][1] + bo1, 0.f);
            float r2 = fmaxf(acc[m][n][2] + bo0, 0.f);
            float r3 = fmaxf(acc[m][n][3] + bo1, 0.f);
            *(float2*)&g_hd[row_lo + col] = make_float2(r0, r1);
            *(float2*)&g_hd[row_hi + col] = make_float2(r2, r3);
            s += r0 + r1 + r2 + r3;
            sq += r0 * r0 + r1 * r1 + r2 * r2 + r3 * r3;
        }
    }
    float* red = sm;
    red[tid] = s; red[256 + tid] = sq;
    __syncthreads();
    for (int st = 128; st > 0; st >>= 1) {
        if (tid < st) { red[tid] += red[tid + st]; red[256 + tid] += red[256 + tid + st]; }
        __syncthreads();
    }
    if (tid == 0) { g_part[blockIdx.x * 2] = red[0]; g_part[blockIdx.x * 2 + 1] = red[256]; }
}

// ---------------- fused fc1 + qkv: 64 px per block; weights via LDG ----------------
#define FQ_SMEM_BYTES ((8192 + 4096) * 4)

__global__ void __launch_bounds__(256, 2) k_fc1qkv(const float* __restrict__ xin,
                                                   const float* __restrict__ nw,
                                                   const float* __restrict__ nb,
                                                   const void* __restrict__ mask, int s,
                                                   float* __restrict__ xout,
                                                   const float* __restrict__ lw,
                                                   const float* __restrict__ lb) {
    extern __shared__ float sm[];
    float* ysh = sm;                  // [64][128] swizzled (fc1 A); later ysh2 [64][64]
    float* xsh = sm + 8192;           // [64][64] xn values
    __shared__ float s_mu, s_rs;
    int tid = threadIdx.x;
    int b = blockIdx.x >> 6;
    int p0 = (blockIdx.x & 63) << 6;
    int warp = tid >> 5, lane = tid & 31;
    int g = lane >> 2, t4 = lane & 3;

    if (tid < 32) {
        float ss = g_part[(b * 32 + tid) * 2];
        float sq = g_part[(b * 32 + tid) * 2 + 1];
        #pragma unroll
        for (int o = 16; o > 0; o >>= 1) {
            ss += __shfl_xor_sync(0xffffffffu, ss, o);
            sq += __shfl_xor_sync(0xffffffffu, sq, o);
        }
        if (tid == 0) {
            const float inv = 1.f / 524288.f;
            float mu = ss * inv;
            s_mu = mu;
            s_rs = rsqrtf(sq * inv - mu * mu + 1e-5f);
        }
    }
    __syncthreads();
    float mu = s_mu, rs = s_rs;

    #pragma unroll
    for (int i = 0; i < 32; i++) {
        int lin = i * 256 + tid;
        int pix = lin >> 7, kk = lin & 127;
        size_t gi = ((size_t)b * NPIX + p0 + pix) * HID + kk;
        int ii = (p0 + pix) * HID + kk;
        float y = (g_hd[gi] - mu) * rs * nw[ii] + nb[ii];
        int half = kk >> 6, kc = kk & 63;
        ysh[pix * 128 + half * 64 + swz_pos(kc, pix & 1)] = __uint_as_float(f2tf32(y));
    }
    __syncthreads();

    {
        int pixBase = (warp & 1) * 32;
        int oBase = (warp >> 1) * 16;

        float acc[2][2][4];
        #pragma unroll
        for (int m = 0; m < 2; m++)
            #pragma unroll
            for (int n = 0; n < 2; n++)
                #pragma unroll
                for (int j = 0; j < 4; j++) acc[m][n][j] = 0.f;

        #pragma unroll
        for (int half = 0; half < 2; half++) {
            #pragma unroll
            for (int j = 0; j < 4; j++) {
                int pibase = t4 * 4 + ((j + t4) & 3);
                float4 av[4];
                #pragma unroll
                for (int r = 0; r < 4; r++) {
                    int pr = pixBase + r * 8 + g;
                    av[r] = *(const float4*)&ysh[pr * 128 + half * 64 + ((pibase ^ (pr & 1)) << 2)];
                }
                uint32_t aH0m0[4] = {__float_as_uint(av[0].x), __float_as_uint(av[1].x),
                                     __float_as_uint(av[0].y), __float_as_uint(av[1].y)};
                uint32_t aH1m0[4] = {__float_as_uint(av[0].z), __float_as_uint(av[1].z),
                                     __float_as_uint(av[0].w), __float_as_uint(av[1].w)};
                uint32_t aH0m1[4] = {__float_as_uint(av[2].x), __float_as_uint(av[3].x),
                                     __float_as_uint(av[2].y), __float_as_uint(av[3].y)};
                uint32_t aH1m1[4] = {__float_as_uint(av[2].z), __float_as_uint(av[3].z),
                                     __float_as_uint(av[2].w), __float_as_uint(av[3].w)};
                #pragma unroll
                for (int n = 0; n < 2; n++) {
                    int o = oBase + n * 8 + g;
                    float4 bv = __ldg((const float4*)&g_FC1swz[o * 128 + half * 64 +
                                                               ((pibase ^ (o & 1)) << 2)]);
                    uint32_t b0 = __float_as_uint(bv.x), b1 = __float_as_uint(bv.y);
                    uint32_t b2 = __float_as_uint(bv.z), b3 = __float_as_uint(bv.w);
                    mma_tf32(acc[0][n], aH0m0, b0, b1);
                    mma_tf32(acc[0][n], aH1m0, b2, b3);
                    mma_tf32(acc[1][n], aH0m1, b0, b1);
                    mma_tf32(acc[1][n], aH1m1, b2, b3);
                }
            }
        }

        int mode = g_maskmode;
        #pragma unroll
        for (int m = 0; m < 2; m++) {
            int p_lo = pixBase + m * 16 + g;
            int p_hi = p_lo + 8;
            size_t gplo = (size_t)b * NPIX + p0 + p_lo;
            size_t gphi = (size_t)b * NPIX + p0 + p_hi;
            size_t milo = (size_t)s * 32768 + gplo;
            size_t mihi = (size_t)s * 32768 + gphi;
            float mvlo, mvhi;
            if (mode) {
                mvlo = ((const unsigned char*)mask)[milo] ? 1.f : 0.f;
                mvhi = ((const unsigned char*)mask)[mihi] ? 1.f : 0.f;
            } else {
                mvlo = ((const unsigned int*)mask)[milo] ? 1.f : 0.f;
                mvhi = ((const unsigned int*)mask)[mihi] ? 1.f : 0.f;
            }
            #pragma unroll
            for (int n = 0; n < 2; n++) {
                int col = oBase + n * 8 + 2 * t4;
                float2 x0 = *(const float2*)&xin[gplo * CCH + col];
                float2 x1 = *(const float2*)&xin[gphi * CCH + col];
                float2 o0 = make_float2(x0.x + acc[m][n][0] * mvlo, x0.y + acc[m][n][1] * mvlo);
                float2 o1 = make_float2(x1.x + acc[m][n][2] * mvhi, x1.y + acc[m][n][3] * mvhi);
                *(float2*)&xout[gplo * CCH + col] = o0;
                *(float2*)&xout[gphi * CCH + col] = o1;
                *(float2*)&xsh[p_lo * 64 + col] = o0;
                *(float2*)&xsh[p_hi * 64 + col] = o1;
            }
        }
    }
    __syncthreads();

    float* ysh2 = sm;     // [64][64] swizzled, overlays ysh (reads complete)

    #pragma unroll
    for (int k = 0; k < 8; k++) {
        int pix = warp * 8 + k;
        float v0 = xsh[pix * 64 + lane], v1 = xsh[pix * 64 + lane + 32];
        float ss = v0 + v1, sq = v0 * v0 + v1 * v1;
        #pragma unroll
        for (int o = 16; o > 0; o >>= 1) {
            ss += __shfl_xor_sync(0xffffffffu, ss, o);
            sq += __shfl_xor_sync(0xffffffffu, sq, o);
        }
        float mu2 = ss * (1.f / 64.f);
        float rsg = rsqrtf(sq * (1.f / 64.f) - mu2 * mu2 + 1e-5f);
        float y0 = (v0 - mu2) * rsg * lw[lane] + lb[lane];
        float y1 = (v1 - mu2) * rsg * lw[lane + 32] + lb[lane + 32];
        ysh2[pix * 64 + swz_pos(lane, pix & 1)] = __uint_as_float(f2tf32(y0));
        ysh2[pix * 64 + swz_pos(lane + 32, pix & 1)] = __uint_as_float(f2tf32(y1));
    }
    __syncthreads();

    {
        int pixBase = (warp & 1) * 32;
        int oBase = (warp >> 1) * 48;

        float acc[2][6][4];
        #pragma unroll
        for (int m = 0; m < 2; m++)
            #pragma unroll
            for (int n = 0; n < 6; n++)
                #pragma unroll
                for (int j = 0; j < 4; j++) acc[m][n][j] = 0.f;

        #pragma unroll
        for (int j = 0; j < 4; j++) {
            int pibase = t4 * 4 + ((j + t4) & 3);
            float4 av[4];
            #pragma unroll
            for (int r = 0; r < 4; r++) {
                int pr = pixBase + r * 8 + g;
                av[r] = *(const float4*)&ysh2[pr * 64 + ((pibase ^ (pr & 1)) << 2)];
            }
            uint32_t aH0m0[4] = {__float_as_uint(av[0].x), __float_as_uint(av[1].x),
                                 __float_as_uint(av[0].y), __float_as_uint(av[1].y)};
            uint32_t aH1m0[4] = {__float_as_uint(av[0].z), __float_as_uint(av[1].z),
                                 __float_as_uint(av[0].w), __float_as_uint(av[1].w)};
            uint32_t aH0m1[4] = {__float_as_uint(av[2].x), __float_as_uint(av[3].x),
                                 __float_as_uint(av[2].y), __float_as_uint(av[3].y)};
            uint32_t aH1m1[4] = {__float_as_uint(av[2].z), __float_as_uint(av[3].z),
                                 __float_as_uint(av[2].w), __float_as_uint(av[3].w)};
            #pragma unroll
            for (int n = 0; n < 6; n++) {
                int o = oBase + n * 8 + g;
                float4 bv = __ldg((const float4*)&g_QKVswz[o * 64 + ((pibase ^ (o & 1)) << 2)]);
                uint32_t b0 = __float_as_uint(bv.x), b1 = __float_as_uint(bv.y);
                uint32_t b2 = __float_as_uint(bv.z), b3 = __float_as_uint(bv.w);
                mma_tf32(acc[0][n], aH0m0, b0, b1);
                mma_tf32(acc[0][n], aH1m0, b2, b3);
                mma_tf32(acc[1][n], aH0m1, b0, b1);
                mma_tf32(acc[1][n], aH1m1, b2, b3);
            }
        }

        #pragma unroll
        for (int m = 0; m < 2; m++) {
            int p_lo = pixBase + m * 16 + g;
            int p_hi = p_lo + 8;
            size_t gplo = (size_t)b * NPIX + p0 + p_lo;
            size_t gphi = (size_t)b * NPIX + p0 + p_hi;
            #pragma unroll
            for (int n = 0; n < 6; n++) {
                int col = oBase + n * 8 + 2 * t4;
                int region = col >> 6;
                int c = col & 63;
                float* dst = (region == 0) ? g_q : (region == 1) ? g_k : g_v;
                *(float2*)&dst[gplo * CCH + c] = make_float2(acc[m][n][0], acc[m][n][1]);
                *(float2*)&dst[gphi * CCH + c] = make_float2(acc[m][n][2], acc[m][n][3]);
            }
        }
    }
}

// ---------------- fused attn + ff, 32px/block, weights via LDG, 5 barriers ----------
#define AF_SMEM_BYTES (12032 * 4)

__global__ void __launch_bounds__(128, 4) k_attn_ff(const float* __restrict__ xn,
                                                    const float* __restrict__ xprev,
                                                    const float* __restrict__ outb,
                                                    const float* __restrict__ lw2,
                                                    const float* __restrict__ lb2,
                                                    const float* __restrict__ b1,
                                                    const float* __restrict__ b2,
                                                    float* __restrict__ xout) {
    extern __shared__ float sm[];
    float* ksh = sm;                  // [64ch][61pos] (dead after attention)
    float* vsh = sm + 3904;
    float* hshp = sm + 4224;          // [32][66] GELU out (in dead kv space)
    float* oshp = sm + 7808;          // [32][66]; aliased as yshp after out-proj
    float* tsh = sm + 9920;           // [32][66] fp32
    int tid = threadIdx.x;
    int b = blockIdx.x >> 7;
    int tile = blockIdx.x & 127;
    int tx0 = (tile & 7) << 3;
    int ty0 = (tile >> 3) << 2;
    int warp = tid >> 5, lane = tid & 31;
    int g = lane >> 2, t4 = lane & 3;
    int mw = warp & 1, nw = warp >> 1;

    #pragma unroll
    for (int i = 0; i < 30; i++) {
        int lin = tid + i * 128;
        int pos = lin >> 6, ch = lin & 63;
        int hy = pos / 10, hx = pos - hy * 10;
        int gy = ty0 + hy - 1, gx = tx0 + hx - 1;
        float kv = 0.f, vv = 0.f;
        if ((unsigned)gy < 64u && (unsigned)gx < 64u) {
            size_t a = ((size_t)b * NPIX + gy * 64 + gx) * CCH + ch;
            kv = g_k[a]; vv = g_v[a];
        }
        ksh[ch * 61 + pos] = kv;
        vsh[ch * 61 + pos] = vv;
    }
    __syncthreads();

    {
        int head = warp, lp = lane;
        int py = lp >> 3, px = lp & 7;
        int gy = ty0 + py, gx = tx0 + px;
        size_t qbase = ((size_t)b * NPIX + gy * 64 + gx) * CCH + head * 16;
        float q[16];
        #pragma unroll
        for (int i = 0; i < 4; i++) {
            float4 t4v = *(const float4*)&g_q[qbase + i * 4];
            q[i * 4] = t4v.x; q[i * 4 + 1] = t4v.y; q[i * 4 + 2] = t4v.z; q[i * 4 + 3] = t4v.w;
        }
        float lg[9];
        #pragma unroll
        for (int t = 0; t < 9; t++) {
            int pos = (py + t / 3) * 10 + px + t % 3;
            float d = 0.f;
            #pragma unroll
            for (int i = 0; i < 16; i++) d = fmaf(q[i], ksh[(head * 16 + i) * 61 + pos], d);
            lg[t] = d * ATT_SCALE;
        }
        float m = lg[0];
        #pragma unroll
        for (int t = 1; t < 9; t++) m = fmaxf(m, lg[t]);
        float e[9], ssum = 0.f;
        #pragma unroll
        for (int t = 0; t < 9; t++) { e[t] = __expf(lg[t] - m); ssum += e[t]; }
        float inv = 1.f / ssum;
        float o[16] = {};
        #pragma unroll
        for (int t = 0; t < 9; t++) {
            int pos = (py + t / 3) * 10 + px + t % 3;
            float a = e[t] * inv;
            #pragma unroll
            for (int i = 0; i < 16; i++) o[i] = fmaf(a, vsh[(head * 16 + i) * 61 + pos], o[i]);
        }
        #pragma unroll
        for (int i = 0; i < 16; i++)
            oshp[lp * 66 + pairpos(head * 16 + i)] = __uint_as_float(f2tf32(o[i]));
    }
    __syncthreads();

    // out-proj (W via LDG) + bias + residual -> tsh
    {
        float acc[4][4] = {{0}};
        gemm_66g(oshp, g_OUTp, mw * 16, nw, g, t4, acc);
        int r0 = mw * 16 + g, r1 = r0 + 8;
        int gp0 = (ty0 + (r0 >> 3)) * 64 + tx0 + (r0 & 7);
        int gp1 = (ty0 + (r1 >> 3)) * 64 + tx0 + (r1 & 7);
        size_t b0a = ((size_t)b * NPIX + gp0) * CCH;
        size_t b1a = ((size_t)b * NPIX + gp1) * CCH;
        #pragma unroll
        for (int n = 0; n < 4; n++) {
            int col = nw * 32 + n * 8 + 2 * t4;
            tsh[r0 * 66 + col]     = acc[n][0] + outb[col]     + xn[b0a + col];
            tsh[r0 * 66 + col + 1] = acc[n][1] + outb[col + 1] + xn[b0a + col + 1];
            tsh[r1 * 66 + col]     = acc[n][2] + outb[col]     + xn[b1a + col];
            tsh[r1 * 66 + col + 1] = acc[n][3] + outb[col + 1] + xn[b1a + col + 1];
        }
    }
    __syncthreads();

    // LN2 -> yshp (aliases oshp)
    float* yshp = oshp;
    #pragma unroll
    for (int k = 0; k < 8; k++) {
        int pix = warp * 8 + k;
        float v0 = tsh[pix * 66 + lane], v1 = tsh[pix * 66 + lane + 32];
        float ss = v0 + v1, sq = v0 * v0 + v1 * v1;
        #pragma unroll
        for (int o = 16; o > 0; o >>= 1) {
            ss += __shfl_xor_sync(0xffffffffu, ss, o);
            sq += __shfl_xor_sync(0xffffffffu, sq, o);
        }
        float mu = ss * (1.f / 64.f);
        float rsg = rsqrtf(sq * (1.f / 64.f) - mu * mu + 1e-5f);
        float y0 = (v0 - mu) * rsg * lw2[lane] + lb2[lane];
        float y1 = (v1 - mu) * rsg * lw2[lane + 32] + lb2[lane + 32];
        yshp[pix * 66 + pairpos(lane)] = __uint_as_float(f2tf32(y0));
        yshp[pix * 66 + pairpos(lane + 32)] = __uint_as_float(f2tf32(y1));
    }
    __syncthreads();

    // ff1 (W via LDG) + bias + GELU -> hshp
    {
        float acc[4][4] = {{0}};
        gemm_66g(yshp, g_FF1p, mw * 16, nw, g, t4, acc);
        int r0 = mw * 16 + g, r1 = r0 + 8;
        #pragma unroll
        for (int n = 0; n < 4; n++) {
            int col = nw * 32 + n * 8 + 2 * t4;
            float bb0 = b1[col], bb1 = b1[col + 1];
            float h0 = acc[n][0] + bb0, h1 = acc[n][1] + bb1;
            float h2 = acc[n][2] + bb0, h3 = acc[n][3] + bb1;
            h0 = 0.5f * h0 * (1.f + erff(h0 * 0.70710678118654752f));
            h1 = 0.5f * h1 * (1.f + erff(h1 * 0.70710678118654752f));
            h2 = 0.5f * h2 * (1.f + erff(h2 * 0.70710678118654752f));
            h3 = 0.5f * h3 * (1.f + erff(h3 * 0.70710678118654752f));
            hshp[r0 * 66 + pairpos(col)]     = __uint_as_float(f2tf32(h0));
            hshp[r0 * 66 + pairpos(col + 1)] = __uint_as_float(f2tf32(h1));
            hshp[r1 * 66 + pairpos(col)]     = __uint_as_float(f2tf32(h2));
            hshp[r1 * 66 + pairpos(col + 1)] = __uint_as_float(f2tf32(h3));
        }
    }
    __syncthreads();

    // ff2 (W via LDG) + bias + residual + ch0 restore -> global
    {
        float acc[4][4] = {{0}};
        gemm_66g(hshp, g_FF2p, mw * 16, nw, g, t4, acc);
        int r0 = mw * 16 + g, r1 = r0 + 8;
        int gp0 = (ty0 + (r0 >> 3)) * 64 + tx0 + (r0 & 7);
        int gp1 = (ty0 + (r1 >> 3)) * 64 + tx0 + (r1 & 7);
        size_t b0a = ((size_t)b * NPIX + gp0) * CCH;
        size_t b1a = ((size_t)b * NPIX + gp1) * CCH;
        #pragma unroll
        for (int n = 0; n < 4; n++) {
            int col = nw * 32 + n * 8 + 2 * t4;
            float v00 = acc[n][0] + b2[col]     + tsh[r0 * 66 + col];
            float v01 = acc[n][1] + b2[col + 1] + tsh[r0 * 66 + col + 1];
            float v10 = acc[n][2] + b2[col]     + tsh[r1 * 66 + col];
            float v11 = acc[n][3] + b2[col + 1] + tsh[r1 * 66 + col + 1];
            if (col == 0) { v00 = xprev[b0a]; v10 = xprev[b1a]; }
            xout[b0a + col]     = v00;
            xout[b0a + col + 1] = v01;
            xout[b1a + col]     = v10;
            xout[b1a + col + 1] = v11;
        }
    }
}

extern "C" void kernel_launch(void* const* d_in, const int* in_sizes, int n_in,
                              void* d_out, int out_size) {
    const float* x = (const float*)d_in[0];
    const void* masks = d_in[1];
    const float* p0_w = (const float*)d_in[2];
    const float* p0_b = (const float*)d_in[3];
    const float* p1_w = (const float*)d_in[4];
    const float* p1_b = (const float*)d_in[5];
    const float* fc0_w = (const float*)d_in[6];
    const float* fc0_b = (const float*)d_in[7];
    const float* fc1_w = (const float*)d_in[8];
    const float* n0w = (const float*)d_in[9];
    const float* n0b = (const float*)d_in[10];
    const float* ln1w = (const float*)d_in[11];
    const float* ln1b = (const float*)d_in[12];
    const float* qkvw = (const float*)d_in[13];
    const float* outw = (const float*)d_in[14];
    const float* outb = (const float*)d_in[15];
    const float* ln2w = (const float*)d_in[16];
    const float* ln2b = (const float*)d_in[17];
    const float* ff1w = (const float*)d_in[18];
    const float* ff1b = (const float*)d_in[19];
    const float* ff2w = (const float*)d_in[20];
    const float* ff2b = (const float*)d_in[21];
    float* out = (float*)d_out;

    cudaFuncSetAttribute(k_conv_mma, cudaFuncAttributeMaxDynamicSharedMemorySize, CONV_SMEM_BYTES);
    cudaFuncSetAttribute(k_fc1qkv, cudaFuncAttributeMaxDynamicSharedMemorySize, FQ_SMEM_BYTES);
    cudaFuncSetAttribute(k_attn_ff, cudaFuncAttributeMaxDynamicSharedMemorySize, AF_SMEM_BYTES);

    k_fold<<<288, 256>>>(fc0_w, fc0_b, p0_w, p0_b, p1_w, p1_b);
    k_prepw<<<48, 256>>>(qkvw, fc1_w, outw, ff1w, ff2w);
    k_maskdetect<<<1, 1024>>>((const unsigned char*)masks, 6 * BATCH * NPIX);

    void* sym = nullptr;
    cudaGetSymbolAddress(&sym, g_xbuf);
    float* buf0 = (float*)sym;
    float* buf1 = buf0 + BATCH * NPIX * CCH;

    const float* cur = x;
    for (int s = 0; s < 6; s++) {
        float* stage = (s & 1) ? buf1 : buf0;
        float* nxt = (s == 5) ? out : stage;
        k_conv_mma<<<256, 256, CONV_SMEM_BYTES>>>(cur);
        k_fc1qkv<<<512, 256, FQ_SMEM_BYTES>>>(cur, n0w, n0b, masks, s, stage, ln1w, ln1b);
        k_attn_ff<<<1024, 128, AF_SMEM_BYTES>>>(stage, cur, outb, ln2w, ln2b,
                                                ff1b, ff2b, nxt);
        cur = nxt;
    }
}